// round 9
// baseline (speedup 1.0000x reference)
#include <cuda_runtime.h>
#include <cuda_bf16.h>
#include <cstddef>
#include <cstdint>

// ---------------- problem constants ----------------
#define U_  1024
#define B_  8
#define D_  512
#define H_  8
#define HD_ 64
#define CL_ 64
#define RC_ 4
#define C_  16
#define R_  64
#define S_  16
#define M_  15
#define Q_  1104
#define KV_ 1103
#define NEG_INF_ (-100000000.0f)
#define SCALING_ 0.125f

// ---------------- helpers ----------------
__device__ __forceinline__ uint32_t smem_u32(const void* p) {
    uint32_t a;
    asm("{ .reg .u64 t; cvta.to.shared.u64 t, %1; cvt.u32.u64 %0, t; }" : "=r"(a) : "l"(p));
    return a;
}
#define SWZ128(o) ((o) ^ (((o) >> 3) & 0x70))

__device__ __forceinline__ void ldmx4(uint32_t* r, uint32_t addr) {
    asm volatile("ldmatrix.sync.aligned.m8n8.x4.shared.b16 {%0,%1,%2,%3}, [%4];"
                 : "=r"(r[0]), "=r"(r[1]), "=r"(r[2]), "=r"(r[3]) : "r"(addr));
}
__device__ __forceinline__ void ldmx4t(uint32_t* r, uint32_t addr) {
    asm volatile("ldmatrix.sync.aligned.m8n8.x4.trans.shared.b16 {%0,%1,%2,%3}, [%4];"
                 : "=r"(r[0]), "=r"(r[1]), "=r"(r[2]), "=r"(r[3]) : "r"(addr));
}
__device__ __forceinline__ void mma16816(float* d, const uint32_t* a,
                                         uint32_t b0, uint32_t b1) {
    asm volatile(
        "mma.sync.aligned.m16n8k16.row.col.f32.bf16.bf16.f32 "
        "{%0,%1,%2,%3}, {%4,%5,%6,%7}, {%8,%9}, {%0,%1,%2,%3};"
        : "+f"(d[0]), "+f"(d[1]), "+f"(d[2]), "+f"(d[3])
        : "r"(a[0]), "r"(a[1]), "r"(a[2]), "r"(a[3]), "r"(b0), "r"(b1));
}
__device__ __forceinline__ void cpa16(uint32_t dst, const void* src) {
    asm volatile("cp.async.cg.shared.global [%0], [%1], 16;" :: "r"(dst), "l"(src));
}
#define CPA_COMMIT() asm volatile("cp.async.commit_group;" ::: "memory")
#define CPA_WAIT1()  asm volatile("cp.async.wait_group 1;" ::: "memory")
#define CPA_WAIT0()  asm volatile("cp.async.wait_group 0;" ::: "memory")

// ---------------- scratch (device globals; no allocs) ----------------
__device__ float g_q[(size_t)Q_ * B_ * D_];
__device__ float g_kv[(size_t)KV_ * B_ * 2 * D_];
__device__ float g_pos[(size_t)192 * D_];
__device__ float g_attn[(size_t)Q_ * B_ * D_];
__device__ float g_bd[(size_t)64 * 1024 * 128];
__device__ float g_sc[(size_t)1024 * 80 * 160];       // compact AC scores
__device__ float g_bu[(size_t)64 * 1104];             // pbu . K per (bh, kv)
__device__ __nv_bfloat16 g_whi[1024 * 512];
__device__ __nv_bfloat16 g_wlo[1024 * 512];
__device__ __nv_bfloat16 g_ahi[(size_t)9216 * 512];
__device__ __nv_bfloat16 g_alo[(size_t)9216 * 512];
__device__ __nv_bfloat16 g_qhi[(size_t)Q_ * B_ * D_];
__device__ __nv_bfloat16 g_qlo[(size_t)Q_ * B_ * D_];
__device__ __nv_bfloat16 g_kvhi[(size_t)KV_ * B_ * 2 * D_];
__device__ __nv_bfloat16 g_kvlo[(size_t)KV_ * B_ * 2 * D_];

// ---------------- kv column mapping ----------------
__device__ __forceinline__ int kv_row_of(int i, int c, int ustart) {
    return (i < c) ? i
         : (i < c + 4 ? M_ + c * 4 + (i - c)
                      : M_ + R_ + ustart + (i - c - 4));
}

// =====================================================================
// Weight split
// =====================================================================
__global__ void conv_w_kernel(const float* __restrict__ src, int n)
{
    int i = blockIdx.x * 256 + threadIdx.x;
    if (i < n) {
        float a = src[i];
        __nv_bfloat16 h = __float2bfloat16(a);
        g_whi[i] = h;
        g_wlo[i] = __float2bfloat16(a - __bfloat162float(h));
    }
}

// =====================================================================
// A split (concat of <=4 row segments)
// =====================================================================
__global__ void conv_a_kernel(const float* __restrict__ A0, const float* __restrict__ A1,
                              const float* __restrict__ A2, const float* __restrict__ A3,
                              int r1, int r2, int r3, int nrows, int dst_row0)
{
    int i = blockIdx.x * 256 + threadIdx.x;
    if (i >= nrows * 128) return;
    int row = i >> 7, c4 = (i & 127) * 4;
    const float* src; int lr;
    if (row < r1)      { src = A0; lr = row; }
    else if (row < r2) { src = A1; lr = row - r1; }
    else if (row < r3) { src = A2; lr = row - r2; }
    else               { src = A3; lr = row - r3; }
    float4 v = *(const float4*)(src + (size_t)lr * 512 + c4);
    float vv[4] = {v.x, v.y, v.z, v.w};
    ushort hi[4], lo[4];
    #pragma unroll
    for (int j = 0; j < 4; j++) {
        __nv_bfloat16 h = __float2bfloat16(vv[j]);
        __nv_bfloat16 l = __float2bfloat16(vv[j] - __bfloat162float(h));
        hi[j] = __bfloat16_as_ushort(h);
        lo[j] = __bfloat16_as_ushort(l);
    }
    size_t o = (size_t)(dst_row0 + row) * 512 + c4;
    *(uint2*)&g_ahi[o] = make_uint2((uint32_t)hi[0] | ((uint32_t)hi[1] << 16),
                                    (uint32_t)hi[2] | ((uint32_t)hi[3] << 16));
    *(uint2*)&g_alo[o] = make_uint2((uint32_t)lo[0] | ((uint32_t)lo[1] << 16),
                                    (uint32_t)lo[2] | ((uint32_t)lo[3] << 16));
}

// =====================================================================
// HMMA GEMM with cp.async pipeline; optional bf16 hi/lo dual-output
// =====================================================================
#define GSM_TOTAL 98304

__global__ __launch_bounds__(256, 2) void gemm_tc_kernel(
    const __nv_bfloat16* __restrict__ Ahi, const __nv_bfloat16* __restrict__ Alo,
    float* __restrict__ Cm, __nv_bfloat16* __restrict__ Chi,
    __nv_bfloat16* __restrict__ Clo,
    int Mr, int ldc, const float* __restrict__ bias)
{
    extern __shared__ char gsm[];
    const uint32_t sb = smem_u32(gsm);
    const int tid = threadIdx.x;
    const int wid = tid >> 5, lane = tid & 31;
    const int wm = wid & 3, wn = wid >> 2;
    const int row0 = blockIdx.y * 128, col0 = blockIdx.x * 128;
    const int car = tid >> 3, cg8 = tid & 7;

    auto issue = [&](int c) {
        const int seg = c >> 3;
        const int k0 = (c & 7) * 64;
        const __nv_bfloat16* asrc = (seg == 1) ? Alo : Ahi;
        const __nv_bfloat16* wsrc = (seg == 2) ? g_wlo : g_whi;
        char* abuf = gsm + (c % 3) * 16384;
        char* bbuf = gsm + 49152 + (c % 3) * 16384;
        #pragma unroll
        for (int t = 0; t < 4; t++) {
            int ar = car + t * 32;
            int gr = row0 + ar; if (gr >= Mr) gr = Mr - 1;
            cpa16(smem_u32(abuf) + SWZ128((uint32_t)(ar * 128 + cg8 * 16)),
                  asrc + (size_t)gr * 512 + k0 + cg8 * 8);
        }
        #pragma unroll
        for (int t = 0; t < 4; t++) {
            int br = car + t * 32;
            cpa16(smem_u32(bbuf) + SWZ128((uint32_t)(br * 128 + cg8 * 16)),
                  wsrc + (size_t)(col0 + br) * 512 + k0 + cg8 * 8);
        }
        CPA_COMMIT();
    };

    float acc[2][8][4] = {};
    issue(0);
    issue(1);

    const int l15 = lane & 15, lh = lane >> 4;
    const int l8 = lane & 7, lg = lane >> 3;

    for (int c = 0; c < 24; c++) {
        if (c < 23) CPA_WAIT1(); else CPA_WAIT0();
        __syncthreads();
        const uint32_t Ab = sb + (c % 3) * 16384;
        const uint32_t Bb = sb + 49152 + (c % 3) * 16384;
        #pragma unroll
        for (int s = 0; s < 4; s++) {
            uint32_t afr[2][4];
            #pragma unroll
            for (int mt = 0; mt < 2; mt++) {
                int r = wm * 32 + mt * 16 + l15;
                uint32_t o = (uint32_t)(r * 128 + s * 32 + lh * 16);
                ldmx4(afr[mt], Ab + SWZ128(o));
            }
            uint32_t bfr[4][4];
            #pragma unroll
            for (int bt = 0; bt < 4; bt++) {
                int n = wn * 64 + bt * 16 + ((lg >> 1) ? 8 : 0) + l8;
                uint32_t o = (uint32_t)(n * 128 + s * 32 + (lg & 1) * 16);
                ldmx4(bfr[bt], Bb + SWZ128(o));
            }
            #pragma unroll
            for (int mt = 0; mt < 2; mt++)
                #pragma unroll
                for (int nt = 0; nt < 8; nt++) {
                    int bt = nt >> 1, sub = nt & 1;
                    mma16816(acc[mt][nt], afr[mt], bfr[bt][2*sub], bfr[bt][2*sub+1]);
                }
        }
        if (c + 2 < 24) issue(c + 2);
    }

    const int quad = lane >> 2, tq = lane & 3;
    #pragma unroll
    for (int mt = 0; mt < 2; mt++) {
        #pragma unroll
        for (int nt = 0; nt < 8; nt++) {
            int gr0 = row0 + wm * 32 + mt * 16 + quad;
            int gc  = col0 + wn * 64 + nt * 8 + tq * 2;
            float b0 = bias ? bias[gc]     : 0.f;
            float b1 = bias ? bias[gc + 1] : 0.f;
            #pragma unroll
            for (int half = 0; half < 2; half++) {
                int gr = gr0 + half * 8;
                if (gr < Mr) {
                    float2 v = {acc[mt][nt][half*2+0] + b0, acc[mt][nt][half*2+1] + b1};
                    *(float2*)&Cm[(size_t)gr * ldc + gc] = v;
                    if (Chi) {
                        __nv_bfloat16 h0 = __float2bfloat16(v.x);
                        __nv_bfloat16 h1 = __float2bfloat16(v.y);
                        __nv_bfloat16 l0 = __float2bfloat16(v.x - __bfloat162float(h0));
                        __nv_bfloat16 l1 = __float2bfloat16(v.y - __bfloat162float(h1));
                        *(uint32_t*)&Chi[(size_t)gr * ldc + gc] =
                            (uint32_t)__bfloat16_as_ushort(h0) | ((uint32_t)__bfloat16_as_ushort(h1) << 16);
                        *(uint32_t*)&Clo[(size_t)gr * ldc + gc] =
                            (uint32_t)__bfloat16_as_ushort(l0) | ((uint32_t)__bfloat16_as_ushort(l1) << 16);
                    }
                }
            }
        }
    }
}

// =====================================================================
// BD kernel: banded qv.pos (+pbv.pos) -> g_bd[bh][1024][128]
// =====================================================================
#define BDSM_FLOATS (64*65 + 64*193 + 192 + 64)

__global__ __launch_bounds__(256) void bd_kernel(const float* __restrict__ pbv)
{
    extern __shared__ float smf[];
    float* qv      = smf;
    float* Pt      = smf + 64 * 65;
    float* bias_vp = Pt + 64 * 193;
    float* pbv_s   = bias_vp + 192;

    const int c = blockIdx.x, bh = blockIdx.y;
    const int b = bh >> 3, h = bh & 7;
    const int tid = threadIdx.x;
    const int pbase = (c == 0) ? 127 : 63;

    for (int idx = tid; idx < 64 * 64; idx += 256) {
        int u = idx >> 6, k = idx & 63;
        qv[u * 65 + k] = g_q[((size_t)(R_ + c * 64 + u) * B_ + b) * D_ + h * 64 + k];
    }
    for (int idx = tid; idx < 191 * 64; idx += 256) {
        int pl = idx >> 6, k = idx & 63;
        Pt[k * 193 + pl] = g_pos[(size_t)pl * D_ + h * 64 + k];
    }
    if (tid < 64) pbv_s[tid] = pbv[h * 64 + tid];
    __syncthreads();

    if (tid < 191) {
        float s = 0.f;
        #pragma unroll 8
        for (int k = 0; k < 64; k++) s += pbv_s[k] * Pt[k * 193 + tid];
        bias_vp[tid] = s;
    }
    __syncthreads();

    const int ty = tid >> 4, tx = tid & 15;
    const int plb = pbase - ty + tx;
    float accb[4][8] = {};
    for (int kk = 0; kk < 64; kk++) {
        float qq[4];
        #pragma unroll
        for (int a = 0; a < 4; a++) qq[a] = qv[(ty + 16 * a) * 65 + kk];
        float pv[11];
        #pragma unroll
        for (int t = 0; t < 11; t++) {
            int pl = plb + 16 * (t - 3);
            pl = (pl < 0) ? 0 : (pl > 190 ? 190 : pl);
            pv[t] = Pt[kk * 193 + pl];
        }
        #pragma unroll
        for (int a = 0; a < 4; a++)
            #pragma unroll
            for (int bb = 0; bb < 8; bb++)
                accb[a][bb] += qq[a] * pv[bb - a + 3];
    }
    float* dst = g_bd + ((size_t)bh * 1024 + c * 64) * 128;
    #pragma unroll
    for (int a = 0; a < 4; a++) {
        int u = ty + 16 * a;
        #pragma unroll
        for (int bb = 0; bb < 8; bb++) {
            int j = tx + 16 * bb;
            int pl = pbase - u + j;
            pl = (pl < 0) ? 0 : (pl > 190 ? 190 : pl);
            dst[(size_t)u * 128 + j] = accb[a][bb] + bias_vp[pl];
        }
    }
}

// =====================================================================
// bu kernel: g_bu[bh][i] = pbu[h] . key[i]  (fp32 exact)
// =====================================================================
__global__ void bu_kernel(const float* __restrict__ pbu)
{
    const int bh = blockIdx.y;
    const int b = bh >> 3, h = bh & 7;
    int i = blockIdx.x * 256 + threadIdx.x;
    if (i >= KV_) return;
    const float4* kp = (const float4*)(g_kv + ((size_t)i * B_ + b) * 1024 + h * 64);
    const float4* pp = (const float4*)(pbu + h * 64);
    float s = 0.f;
    #pragma unroll 4
    for (int k4 = 0; k4 < 16; k4++) {
        float4 kvv = kp[k4];
        float4 pv = pp[k4];
        s += pv.x * kvv.x + pv.y * kvv.y + pv.z * kvv.z + pv.w * kvv.w;
    }
    g_bu[(size_t)bh * 1104 + i] = s;
}

// =====================================================================
// AC kernel: compact scores = Q.K^T via HMMA, 3 split passes.
// grid (16, 64), 256 thr, ~70KB smem -> 2 CTA/SM.
// smem: QHI 0 (80x128), QLO 10240, KHI 20480 (192x128), KLO 45056
// =====================================================================
#define AC_QHI 0
#define AC_QLO 10240
#define AC_KHI 20480
#define AC_KLO 45056
#define AC_TOTAL 69632

__global__ __launch_bounds__(256, 2) void ac_kernel()
{
    extern __shared__ char asm_[];
    const uint32_t sb = smem_u32(asm_);
    const int c = blockIdx.x, bh = blockIdx.y;
    const int b = bh >> 3, h = bh & 7;
    const int tid = threadIdx.x;
    const int wid = tid >> 5, lane = tid & 31;
    const int ustart = (c == 0) ? 0 : (c - 1) * CL_;
    const int ncols = c + 4 + ((c == 0) ? 64 : 128);

    // ---- cp.async: Q rows (69), K rows (ncols), hi+lo ----
    for (int idx = tid; idx < 69 * 8; idx += 256) {
        int r = idx >> 3, ch = idx & 7;
        int qrow = (r < 4) ? c * 4 + r
                 : (r < 68 ? R_ + c * 64 + (r - 4) : R_ + U_ + c);
        size_t go = ((size_t)qrow * B_ + b) * 512 + h * 64 + ch * 8;
        uint32_t so = SWZ128((uint32_t)(r * 128 + ch * 16));
        cpa16(sb + AC_QHI + so, g_qhi + go);
        cpa16(sb + AC_QLO + so, g_qlo + go);
    }
    for (int idx = tid; idx < ncols * 8; idx += 256) {
        int i = idx >> 3, ch = idx & 7;
        int kvrow = kv_row_of(i, c, ustart);
        size_t go = ((size_t)kvrow * B_ + b) * 1024 + h * 64 + ch * 8;
        uint32_t so = SWZ128((uint32_t)(i * 128 + ch * 16));
        cpa16(sb + AC_KHI + so, g_kvhi + go);
        cpa16(sb + AC_KLO + so, g_kvlo + go);
    }
    CPA_COMMIT();
    CPA_WAIT0();
    __syncthreads();

    const int wm = wid >> 2, wn = wid & 3;
    const int l15 = lane & 15, lh = lane >> 4;
    const int l8 = lane & 7, lg = lane >> 3;
    const int quad = lane >> 2, tq = lane & 3;

    float acc[3][6][4] = {};
    #pragma unroll
    for (int pass = 0; pass < 3; pass++) {
        const uint32_t Ab = sb + ((pass == 1) ? AC_QLO : AC_QHI);
        const uint32_t Bb = sb + ((pass == 2) ? AC_KLO : AC_KHI);
        #pragma unroll
        for (int s = 0; s < 4; s++) {
            uint32_t afr[3][4];
            #pragma unroll
            for (int mi = 0; mi < 3; mi++) {
                int m = wm + mi * 2;             // wm=0: 0,2,4; wm=1: 1,3,(5 clamp)
                if (m > 4) m = 4;
                int r = m * 16 + l15;
                ldmx4(afr[mi], Ab + SWZ128((uint32_t)(r * 128 + s * 32 + lh * 16)));
            }
            uint32_t bfr[3][4];
            #pragma unroll
            for (int nt = 0; nt < 3; nt++) {
                int n = wn * 48 + nt * 16 + ((lg >> 1) ? 8 : 0) + l8;
                ldmx4(bfr[nt], Bb + SWZ128((uint32_t)(n * 128 + s * 32 + (lg & 1) * 16)));
            }
            #pragma unroll
            for (int mi = 0; mi < 3; mi++)
                #pragma unroll
                for (int nt = 0; nt < 3; nt++) {
                    mma16816(acc[mi][nt*2+0], afr[mi], bfr[nt][0], bfr[nt][1]);
                    mma16816(acc[mi][nt*2+1], afr[mi], bfr[nt][2], bfr[nt][3]);
                }
        }
    }

    // ---- store compact scores (80 x 160 fp32) ----
    float* dst = g_sc + (size_t)(bh * 16 + c) * 12800;
    #pragma unroll
    for (int mi = 0; mi < 3; mi++) {
        int m = wm + mi * 2;
        if (m > 4) continue;                     // wm=1,mi=2 duplicate -> skip
        int r0 = m * 16 + quad;
        #pragma unroll
        for (int n8 = 0; n8 < 6; n8++) {
            int col = wn * 48 + (n8 >> 1) * 16 + (n8 & 1) * 8 + tq * 2;
            if (col < 160) {
                *(float2*)&dst[(size_t)r0 * 160 + col] =
                    make_float2(acc[mi][n8][0], acc[mi][n8][1]);
                *(float2*)&dst[(size_t)(r0 + 8) * 160 + col] =
                    make_float2(acc[mi][n8][2], acc[mi][n8][3]);
            }
        }
    }
}

// =====================================================================
// PV kernel: softmax (g_sc + g_bu + g_bd + masks) -> P hi/lo smem,
// then P.V via HMMA (.trans V), 3 passes. ~105KB smem -> 2 CTA/SM.
// smem: PHI 0 (80x400B), PLO 32000, VHI 64000 (160x128), VLO 84480
// =====================================================================
#define PV_PHI 0
#define PV_PLO 32000
#define PV_VHI 64000
#define PV_VLO 84480
#define PV_TOTAL 104960

__global__ __launch_bounds__(256, 2) void pv_kernel(const int* __restrict__ lengths)
{
    extern __shared__ char psm[];
    const uint32_t sb = smem_u32(psm);
    const int c = blockIdx.x, bh = blockIdx.y;
    const int b = bh >> 3, h = bh & 7;
    const int tid = threadIdx.x;
    const int wid = tid >> 5, lane = tid & 31;
    const int ustart = (c == 0) ? 0 : (c - 1) * CL_;
    const int ncols = c + 4 + ((c == 0) ? 64 : 128);
    const int len_b = lengths[b];

    // ---- zero P buffers + V pad rows ----
    {
        uint4 z = make_uint4(0, 0, 0, 0);
        for (int i = tid * 16; i < 64000; i += 256 * 16)
            *(uint4*)(psm + PV_PHI + i) = z;
        for (int i = tid * 16; i < (160 - ncols) * 128; i += 256 * 16) {
            *(uint4*)(psm + PV_VHI + ncols * 128 + i) = z;
            *(uint4*)(psm + PV_VLO + ncols * 128 + i) = z;
        }
    }
    // ---- cp.async V rows hi/lo ----
    for (int idx = tid; idx < ncols * 8; idx += 256) {
        int i = idx >> 3, ch = idx & 7;
        int kvrow = kv_row_of(i, c, ustart);
        size_t go = ((size_t)kvrow * B_ + b) * 1024 + 512 + h * 64 + ch * 8;
        uint32_t so = SWZ128((uint32_t)(i * 128 + ch * 16));
        cpa16(sb + PV_VHI + so, g_kvhi + go);
        cpa16(sb + PV_VLO + so, g_kvlo + go);
    }
    CPA_COMMIT();
    __syncthreads();   // P zeroing visible before softmax writes

    // ---- softmax: warp per row ----
    {
        const float* scb = g_sc + (size_t)(bh * 16 + c) * 12800;
        const float* bub = g_bu + (size_t)bh * 1104;
        const int limit_j = len_b - ustart;
        const int uc0 = c + 4;
        for (int r = wid; r < 69; r += 8) {
            const bool is_utt = (r >= 4) && (r < 68);
            const float* bdrow = g_bd + ((size_t)bh * 1024 + c * 64 + (r - 4)) * 128;
            float vals[5];
            float mx = -3.4e38f;
            #pragma unroll
            for (int g = 0; g < 5; g++) {
                int i = lane + 32 * g;
                float v = -3.4e38f;
                if (i < ncols) {
                    int kvrow = kv_row_of(i, c, ustart);
                    float s = scb[(size_t)r * 160 + i] + bub[kvrow];
                    if (i >= uc0) {
                        int j = i - uc0;
                        if (is_utt) s += bdrow[j];
                        v = (j >= limit_j) ? NEG_INF_ : s * SCALING_;
                    } else {
                        v = s * SCALING_;
                    }
                }
                vals[g] = v;
                mx = fmaxf(mx, v);
            }
            #pragma unroll
            for (int o = 16; o > 0; o >>= 1) mx = fmaxf(mx, __shfl_xor_sync(~0u, mx, o));
            float sum = 0.f;
            #pragma unroll
            for (int g = 0; g < 5; g++) {
                float e = __expf(vals[g] - mx);
                vals[g] = e;
                sum += e;
            }
            #pragma unroll
            for (int o = 16; o > 0; o >>= 1) sum += __shfl_xor_sync(~0u, sum, o);
            float inv = 1.f / sum;
            #pragma unroll
            for (int g = 0; g < 5; g++) {
                int i = lane + 32 * g;
                if (i < ncols) {
                    float p = vals[g] * inv;
                    __nv_bfloat16 hp = __float2bfloat16(p);
                    __nv_bfloat16 lp = __float2bfloat16(p - __bfloat162float(hp));
                    *(ushort*)(psm + PV_PHI + r * 400 + i * 2) = __bfloat16_as_ushort(hp);
                    *(ushort*)(psm + PV_PLO + r * 400 + i * 2) = __bfloat16_as_ushort(lp);
                }
            }
        }
    }
    CPA_WAIT0();
    __syncthreads();

    // ---- PV: out = P.V via HMMA ----
    const int wm = wid >> 2, wn = wid & 3;
    const int l15 = lane & 15, lh = lane >> 4;
    const int quad = lane >> 2, tq = lane & 3;
    {
        float accp[3][2][4] = {};
        #pragma unroll
        for (int pass = 0; pass < 3; pass++) {
            const uint32_t Ab = sb + ((pass == 1) ? PV_PLO : PV_PHI);
            const uint32_t Bb = sb + ((pass == 2) ? PV_VLO : PV_VHI);
            #pragma unroll
            for (int kk = 0; kk < 10; kk++) {
                uint32_t afr[3][4];
                #pragma unroll
                for (int mi = 0; mi < 3; mi++) {
                    int m = wm + mi * 2;
                    if (m > 4) m = 4;
                    ldmx4(afr[mi], Ab + (uint32_t)((m * 16 + l15) * 400 + kk * 32 + lh * 16));
                }
                uint32_t bfr[4];
                ldmx4t(bfr, Bb + SWZ128((uint32_t)((kk * 16 + l15) * 128 + wn * 32 + lh * 16)));
                #pragma unroll
                for (int mi = 0; mi < 3; mi++) {
                    mma16816(accp[mi][0], afr[mi], bfr[0], bfr[1]);
                    mma16816(accp[mi][1], afr[mi], bfr[2], bfr[3]);
                }
            }
        }
        #pragma unroll
        for (int mi = 0; mi < 3; mi++) {
            int m = wm + mi * 2;
            if (m > 4) continue;
            int r0 = m * 16 + quad;
            #pragma unroll
            for (int half = 0; half < 2; half++) {
                int r = r0 + half * 8;
                if (r < 69) {
                    int qrow = (r < 4) ? c * 4 + r
                             : (r < 68 ? R_ + c * 64 + (r - 4) : R_ + U_ + c);
                    float* dstp = g_attn + ((size_t)qrow * B_ + b) * 512 + h * 64;
                    #pragma unroll
                    for (int n = 0; n < 2; n++) {
                        int d = wn * 16 + n * 8 + tq * 2;
                        *(float2*)(dstp + d) =
                            make_float2(accp[mi][n][half*2+0], accp[mi][n][half*2+1]);
                    }
                }
            }
        }
    }
}

// ---------------- out_mem = clip(attn[R+U:], -10, 10) ----------------
__global__ void clip_kernel(float* __restrict__ out)
{
    const size_t off = (size_t)(R_ + U_) * B_ * D_;
    int i = blockIdx.x * 256 + threadIdx.x;
    float v = g_attn[off + i];
    out[off + i] = fminf(10.f, fmaxf(-10.f, v));
}

// ---------------- launch ----------------
extern "C" void kernel_launch(void* const* d_in, const int* in_sizes, int n_in,
                              void* d_out, int out_size)
{
    const float* utt    = (const float*)d_in[0];
    const int*   lens   = (const int*)  d_in[1];
    const float* rc     = (const float*)d_in[2];
    const float* summ   = (const float*)d_in[3];
    const float* mem    = (const float*)d_in[4];
    const float* pos_e  = (const float*)d_in[6];
    const float* W_kv   = (const float*)d_in[7];
    const float* b_kv   = (const float*)d_in[8];
    const float* W_q    = (const float*)d_in[9];
    const float* b_q    = (const float*)d_in[10];
    const float* W_out  = (const float*)d_in[11];
    const float* b_out  = (const float*)d_in[12];
    const float* W_pos  = (const float*)d_in[13];
    const float* pbu    = (const float*)d_in[14];
    const float* pbv    = (const float*)d_in[15];
    float* out = (float*)d_out;

    float *q_buf, *kv_buf, *pos_buf, *attn_buf;
    __nv_bfloat16 *ahi, *alo, *qhi, *qlo, *kvhi, *kvlo;
    cudaGetSymbolAddress((void**)&q_buf,    g_q);
    cudaGetSymbolAddress((void**)&kv_buf,   g_kv);
    cudaGetSymbolAddress((void**)&pos_buf,  g_pos);
    cudaGetSymbolAddress((void**)&attn_buf, g_attn);
    cudaGetSymbolAddress((void**)&ahi,      g_ahi);
    cudaGetSymbolAddress((void**)&alo,      g_alo);
    cudaGetSymbolAddress((void**)&qhi,      g_qhi);
    cudaGetSymbolAddress((void**)&qlo,      g_qlo);
    cudaGetSymbolAddress((void**)&kvhi,     g_kvhi);
    cudaGetSymbolAddress((void**)&kvlo,     g_kvlo);

    const size_t SMEM_BD = (size_t)BDSM_FLOATS * 4;
    cudaFuncSetAttribute(bd_kernel,
                         cudaFuncAttributeMaxDynamicSharedMemorySize, (int)SMEM_BD);
    cudaFuncSetAttribute(gemm_tc_kernel,
                         cudaFuncAttributeMaxDynamicSharedMemorySize, GSM_TOTAL);
    cudaFuncSetAttribute(ac_kernel,
                         cudaFuncAttributeMaxDynamicSharedMemorySize, AC_TOTAL);
    cudaFuncSetAttribute(pv_kernel,
                         cudaFuncAttributeMaxDynamicSharedMemorySize, PV_TOTAL);

    const dim3 blk(256);
    const float* pos_src = pos_e + (size_t)(U_ - 128) * D_;

    // ---- A conversion ----
    conv_a_kernel<<<dim3((8952 * 128 + 255) / 256), blk>>>(
        mem, rc, utt, summ, 120, 632, 8824, 8952, 0);
    conv_a_kernel<<<dim3((191 * 128 + 255) / 256), blk>>>(
        pos_src, pos_src, pos_src, pos_src, 191, 191, 191, 191, 8952);

    // ---- projections ----
    conv_w_kernel<<<dim3(1024), blk>>>(W_q, 512 * 512);
    gemm_tc_kernel<<<dim3(4, 69), blk, GSM_TOTAL>>>(
        ahi + (size_t)120 * 512, alo + (size_t)120 * 512,
        q_buf, qhi, qlo, Q_ * B_, D_, b_q);

    conv_w_kernel<<<dim3(2048), blk>>>(W_kv, 1024 * 512);
    gemm_tc_kernel<<<dim3(8, 69), blk, GSM_TOTAL>>>(
        ahi, alo, kv_buf, kvhi, kvlo, KV_ * B_, 2 * D_, b_kv);

    conv_w_kernel<<<dim3(1024), blk>>>(W_pos, 512 * 512);
    gemm_tc_kernel<<<dim3(4, 2), blk, GSM_TOTAL>>>(
        ahi + (size_t)8952 * 512, alo + (size_t)8952 * 512,
        pos_buf, nullptr, nullptr, 191, D_, nullptr);

    // ---- attention pieces ----
    bu_kernel<<<dim3(5, 64), blk>>>(pbu);
    bd_kernel<<<dim3(C_, 64), blk, SMEM_BD>>>(pbv);
    ac_kernel<<<dim3(C_, 64), blk, AC_TOTAL>>>();
    pv_kernel<<<dim3(C_, 64), blk, PV_TOTAL>>>(lens);

    // ---- output projection ----
    conv_a_kernel<<<dim3((8704 * 128 + 255) / 256), blk>>>(
        attn_buf, attn_buf, attn_buf, attn_buf, 8704, 8704, 8704, 8704, 0);
    conv_w_kernel<<<dim3(1024), blk>>>(W_out, 512 * 512);
    gemm_tc_kernel<<<dim3(4, 68), blk, GSM_TOTAL>>>(
        ahi, alo, out, nullptr, nullptr, (R_ + U_) * B_, D_, b_out);
    clip_kernel<<<dim3(256), blk>>>(out);
}

// round 10
// speedup vs baseline: 1.1861x; 1.1861x over previous
#include <cuda_runtime.h>
#include <cuda_bf16.h>
#include <cstddef>
#include <cstdint>

// ---------------- problem constants ----------------
#define U_  1024
#define B_  8
#define D_  512
#define H_  8
#define HD_ 64
#define CL_ 64
#define RC_ 4
#define C_  16
#define R_  64
#define S_  16
#define M_  15
#define Q_  1104
#define KV_ 1103
#define NEG_INF_ (-100000000.0f)
#define SCALING_ 0.125f

// ---------------- packed f32x2 helpers ----------------
typedef unsigned long long u64t;
__device__ __forceinline__ u64t pk2(float v) {
    u64t r; asm("mov.b64 %0, {%1, %1};" : "=l"(r) : "f"(v)); return r;
}
__device__ __forceinline__ void fma2(u64t& d, u64t a, u64t b) {
    asm("fma.rn.f32x2 %0, %1, %2, %0;" : "+l"(d) : "l"(a), "l"(b));
}
__device__ __forceinline__ u64t add2(u64t a, u64t b) {
    u64t r; asm("add.rn.f32x2 %0, %1, %2;" : "=l"(r) : "l"(a), "l"(b)); return r;
}
__device__ __forceinline__ float2 upk(u64t v) {
    float2 f; asm("mov.b64 {%0, %1}, %2;" : "=f"(f.x), "=f"(f.y) : "l"(v)); return f;
}

// ---------------- mma / async helpers ----------------
__device__ __forceinline__ uint32_t smem_u32(const void* p) {
    uint32_t a;
    asm("{ .reg .u64 t; cvta.to.shared.u64 t, %1; cvt.u32.u64 %0, t; }" : "=r"(a) : "l"(p));
    return a;
}
#define SWZ128(o) ((o) ^ (((o) >> 3) & 0x70))

__device__ __forceinline__ void ldmx4(uint32_t* r, uint32_t addr) {
    asm volatile("ldmatrix.sync.aligned.m8n8.x4.shared.b16 {%0,%1,%2,%3}, [%4];"
                 : "=r"(r[0]), "=r"(r[1]), "=r"(r[2]), "=r"(r[3]) : "r"(addr));
}
__device__ __forceinline__ void mma16816(float* d, const uint32_t* a,
                                         uint32_t b0, uint32_t b1) {
    asm volatile(
        "mma.sync.aligned.m16n8k16.row.col.f32.bf16.bf16.f32 "
        "{%0,%1,%2,%3}, {%4,%5,%6,%7}, {%8,%9}, {%0,%1,%2,%3};"
        : "+f"(d[0]), "+f"(d[1]), "+f"(d[2]), "+f"(d[3])
        : "r"(a[0]), "r"(a[1]), "r"(a[2]), "r"(a[3]), "r"(b0), "r"(b1));
}
__device__ __forceinline__ void cpa16(uint32_t dst, const void* src) {
    asm volatile("cp.async.cg.shared.global [%0], [%1], 16;" :: "r"(dst), "l"(src));
}
#define CPA_COMMIT() asm volatile("cp.async.commit_group;" ::: "memory")
#define CPA_WAIT1()  asm volatile("cp.async.wait_group 1;" ::: "memory")
#define CPA_WAIT0()  asm volatile("cp.async.wait_group 0;" ::: "memory")

// ---------------- scratch (device globals; no allocs) ----------------
__device__ float g_q[(size_t)Q_ * B_ * D_];
__device__ float g_kv[(size_t)KV_ * B_ * 2 * D_];
__device__ float g_pos[(size_t)192 * D_];
__device__ float g_attn[(size_t)Q_ * B_ * D_];
__device__ float g_bd[(size_t)64 * 1024 * 128];
__device__ float g_bu[(size_t)64 * 1104];
// weight regions (rows): W_q 0..511 | W_kv 512..1535 | W_out 1536..2047 | W_pos 2048..2559
__device__ __nv_bfloat16 g_whi[(size_t)2560 * 512];
__device__ __nv_bfloat16 g_wlo[(size_t)2560 * 512];
// A concat: [mem 0-119 | rc 120-631 | utt 632-8823 | summ 8824-8951 | pos 8952-9142]
// (rows 0..8703 are later overwritten by the attention output for the out-proj)
__device__ __nv_bfloat16 g_ahi[(size_t)9216 * 512];
__device__ __nv_bfloat16 g_alo[(size_t)9216 * 512];

// ---------------- kv column mapping ----------------
__device__ __forceinline__ int kv_row_of(int i, int c, int ustart) {
    return (i < c) ? i
         : (i < c + 4 ? M_ + c * 4 + (i - c)
                      : M_ + R_ + ustart + (i - c - 4));
}

// =====================================================================
// All-weights split: one launch, 4 regions
// =====================================================================
__global__ void conv_w_all(const float* __restrict__ Wq, const float* __restrict__ Wkv,
                           const float* __restrict__ Wout, const float* __restrict__ Wpos)
{
    int i = blockIdx.x * 256 + threadIdx.x;   // 2560*512 total
    int row = i >> 9, col = i & 511;
    const float* src; int lr;
    if (row < 512)       { src = Wq;   lr = row; }
    else if (row < 1536) { src = Wkv;  lr = row - 512; }
    else if (row < 2048) { src = Wout; lr = row - 1536; }
    else                 { src = Wpos; lr = row - 2048; }
    float a = src[(size_t)lr * 512 + col];
    __nv_bfloat16 h = __float2bfloat16(a);
    g_whi[i] = h;
    g_wlo[i] = __float2bfloat16(a - __bfloat162float(h));
}

// =====================================================================
// A split (concat of <=4 row segments)
// =====================================================================
__global__ void conv_a_kernel(const float* __restrict__ A0, const float* __restrict__ A1,
                              const float* __restrict__ A2, const float* __restrict__ A3,
                              int r1, int r2, int r3, int nrows, int dst_row0)
{
    int i = blockIdx.x * 256 + threadIdx.x;
    if (i >= nrows * 128) return;
    int row = i >> 7, c4 = (i & 127) * 4;
    const float* src; int lr;
    if (row < r1)      { src = A0; lr = row; }
    else if (row < r2) { src = A1; lr = row - r1; }
    else if (row < r3) { src = A2; lr = row - r2; }
    else               { src = A3; lr = row - r3; }
    float4 v = *(const float4*)(src + (size_t)lr * 512 + c4);
    float vv[4] = {v.x, v.y, v.z, v.w};
    ushort hi[4], lo[4];
    #pragma unroll
    for (int j = 0; j < 4; j++) {
        __nv_bfloat16 h = __float2bfloat16(vv[j]);
        __nv_bfloat16 l = __float2bfloat16(vv[j] - __bfloat162float(h));
        hi[j] = __bfloat16_as_ushort(h);
        lo[j] = __bfloat16_as_ushort(l);
    }
    size_t o = (size_t)(dst_row0 + row) * 512 + c4;
    *(uint2*)&g_ahi[o] = make_uint2((uint32_t)hi[0] | ((uint32_t)hi[1] << 16),
                                    (uint32_t)hi[2] | ((uint32_t)hi[3] << 16));
    *(uint2*)&g_alo[o] = make_uint2((uint32_t)lo[0] | ((uint32_t)lo[1] << 16),
                                    (uint32_t)lo[2] | ((uint32_t)lo[3] << 16));
}

// =====================================================================
// Shared GEMM mainloop (macro-free duplication kept minimal):
// 128x128 tile, cp.async 3-stage, 24 chunks (3 split-precision passes).
// =====================================================================
#define GSM_TOTAL 98304

#define GEMM_MAINLOOP(AHI, ALO, WHI, WLO, MRTOT)                                    \
    float acc[2][8][4] = {};                                                        \
    {                                                                               \
        auto issue = [&](int cc) {                                                  \
            const int seg = cc >> 3;                                                \
            const int k0 = (cc & 7) * 64;                                           \
            const __nv_bfloat16* asrc = (seg == 1) ? (ALO) : (AHI);                 \
            const __nv_bfloat16* wsrc = (seg == 2) ? (WLO) : (WHI);                 \
            char* abuf = gsm + (cc % 3) * 16384;                                    \
            char* bbuf = gsm + 49152 + (cc % 3) * 16384;                            \
            _Pragma("unroll")                                                       \
            for (int t = 0; t < 4; t++) {                                           \
                int ar = car + t * 32;                                              \
                int gr = row0 + ar; if (gr >= (MRTOT)) gr = (MRTOT) - 1;            \
                cpa16(smem_u32(abuf) + SWZ128((uint32_t)(ar * 128 + cg8 * 16)),     \
                      asrc + (size_t)gr * 512 + k0 + cg8 * 8);                      \
            }                                                                       \
            _Pragma("unroll")                                                       \
            for (int t = 0; t < 4; t++) {                                           \
                int br = car + t * 32;                                              \
                cpa16(smem_u32(bbuf) + SWZ128((uint32_t)(br * 128 + cg8 * 16)),     \
                      wsrc + (size_t)(col0 + br) * 512 + k0 + cg8 * 8);             \
            }                                                                       \
            CPA_COMMIT();                                                           \
        };                                                                          \
        issue(0);                                                                   \
        issue(1);                                                                   \
        const int l15 = lane & 15, lh = lane >> 4;                                  \
        const int l8 = lane & 7, lg = lane >> 3;                                    \
        for (int cc = 0; cc < 24; cc++) {                                           \
            if (cc < 23) CPA_WAIT1(); else CPA_WAIT0();                             \
            __syncthreads();                                                        \
            const uint32_t Ab = sb + (cc % 3) * 16384;                              \
            const uint32_t Bb = sb + 49152 + (cc % 3) * 16384;                      \
            _Pragma("unroll")                                                       \
            for (int s = 0; s < 4; s++) {                                           \
                uint32_t afr[2][4];                                                 \
                _Pragma("unroll")                                                   \
                for (int mt = 0; mt < 2; mt++) {                                    \
                    int r = wm * 32 + mt * 16 + l15;                                \
                    ldmx4(afr[mt], Ab + SWZ128((uint32_t)(r * 128 + s * 32 + lh * 16))); \
                }                                                                   \
                uint32_t bfr[4][4];                                                 \
                _Pragma("unroll")                                                   \
                for (int bt = 0; bt < 4; bt++) {                                    \
                    int n = wn * 64 + bt * 16 + ((lg >> 1) ? 8 : 0) + l8;           \
                    ldmx4(bfr[bt], Bb + SWZ128((uint32_t)(n * 128 + s * 32 + (lg & 1) * 16))); \
                }                                                                   \
                _Pragma("unroll")                                                   \
                for (int mt = 0; mt < 2; mt++)                                      \
                    _Pragma("unroll")                                               \
                    for (int nt = 0; nt < 8; nt++) {                                \
                        int bt = nt >> 1, sub = nt & 1;                             \
                        mma16816(acc[mt][nt], afr[mt], bfr[bt][2*sub], bfr[bt][2*sub+1]); \
                    }                                                               \
            }                                                                       \
            if (cc + 2 < 24) issue(cc + 2);                                         \
        }                                                                           \
    }

// ---- generic GEMM (pos / out projections) ----
__global__ __launch_bounds__(256, 2) void gemm_tc_kernel(
    const __nv_bfloat16* __restrict__ Ahi, const __nv_bfloat16* __restrict__ Alo,
    const __nv_bfloat16* __restrict__ Whib, const __nv_bfloat16* __restrict__ Wlob,
    float* __restrict__ Cm, int Mr, int ldc, const float* __restrict__ bias)
{
    extern __shared__ char gsm[];
    const uint32_t sb = smem_u32(gsm);
    const int tid = threadIdx.x;
    const int wid = tid >> 5, lane = tid & 31;
    const int wm = wid & 3, wn = wid >> 2;
    const int row0 = blockIdx.y * 128, col0 = blockIdx.x * 128;
    const int car = tid >> 3, cg8 = tid & 7;

    GEMM_MAINLOOP(Ahi, Alo, Whib, Wlob, Mr)

    const int quad = lane >> 2, tq = lane & 3;
    #pragma unroll
    for (int mt = 0; mt < 2; mt++) {
        #pragma unroll
        for (int nt = 0; nt < 8; nt++) {
            int gr0 = row0 + wm * 32 + mt * 16 + quad;
            int gc  = col0 + wn * 64 + nt * 8 + tq * 2;
            float b0 = bias ? bias[gc]     : 0.f;
            float b1 = bias ? bias[gc + 1] : 0.f;
            #pragma unroll
            for (int half = 0; half < 2; half++) {
                int gr = gr0 + half * 8;
                if (gr < Mr) {
                    float2 v = {acc[mt][nt][half*2+0] + b0, acc[mt][nt][half*2+1] + b1};
                    *(float2*)&Cm[(size_t)gr * ldc + gc] = v;
                }
            }
        }
    }
}

// ---- fused Q+KV GEMM: A rows 0..8951, N = 1536 (cols 0..511 -> Q, rest -> KV) ----
__global__ __launch_bounds__(256, 2) void gemm_qkv_kernel(
    const float* __restrict__ b_q, const float* __restrict__ b_kv)
{
    extern __shared__ char gsm[];
    const uint32_t sb = smem_u32(gsm);
    const int tid = threadIdx.x;
    const int wid = tid >> 5, lane = tid & 31;
    const int wm = wid & 3, wn = wid >> 2;
    const int row0 = blockIdx.y * 128, col0 = blockIdx.x * 128;
    const int car = tid >> 3, cg8 = tid & 7;

    GEMM_MAINLOOP(g_ahi, g_alo, g_whi, g_wlo, 8952)

    const int quad = lane >> 2, tq = lane & 3;
    const bool is_q = (col0 < 512);
    #pragma unroll
    for (int mt = 0; mt < 2; mt++) {
        #pragma unroll
        for (int nt = 0; nt < 8; nt++) {
            int gr0 = row0 + wm * 32 + mt * 16 + quad;
            int gc  = col0 + wn * 64 + nt * 8 + tq * 2;
            #pragma unroll
            for (int half = 0; half < 2; half++) {
                int gr = gr0 + half * 8;
                if (gr >= 8952) continue;
                float2 v = {acc[mt][nt][half*2+0], acc[mt][nt][half*2+1]};
                if (is_q) {
                    int qr = gr - 120;
                    if (qr >= 0) {
                        v.x += b_q[gc]; v.y += b_q[gc + 1];
                        *(float2*)&g_q[(size_t)qr * 512 + gc] = v;
                    }
                } else {
                    int kc = gc - 512;
                    if (gr < 8824) {
                        v.x += b_kv[kc]; v.y += b_kv[kc + 1];
                        *(float2*)&g_kv[(size_t)gr * 1024 + kc] = v;
                    }
                }
            }
        }
    }
}

// =====================================================================
// bu kernel: g_bu[bh][i] = pbu[h] . key[i]
// =====================================================================
__global__ void bu_kernel(const float* __restrict__ pbu)
{
    const int bh = blockIdx.y;
    const int b = bh >> 3, h = bh & 7;
    int i = blockIdx.x * 256 + threadIdx.x;
    if (i >= KV_) return;
    const float4* kp = (const float4*)(g_kv + ((size_t)i * B_ + b) * 1024 + h * 64);
    const float4* pp = (const float4*)(pbu + h * 64);
    float s = 0.f;
    #pragma unroll 4
    for (int k4 = 0; k4 < 16; k4++) {
        float4 kvv = kp[k4];
        float4 pv = pp[k4];
        s += pv.x * kvv.x + pv.y * kvv.y + pv.z * kvv.z + pv.w * kvv.w;
    }
    g_bu[(size_t)bh * 1104 + i] = s;
}

// =====================================================================
// BD kernel: banded qv.pos (+pbv.pos) -> g_bd[bh][1024][128]
// =====================================================================
#define BDSM_FLOATS (64*65 + 64*193 + 192 + 64)

__global__ __launch_bounds__(256) void bd_kernel(const float* __restrict__ pbv)
{
    extern __shared__ float smf[];
    float* qv      = smf;
    float* Pt      = smf + 64 * 65;
    float* bias_vp = Pt + 64 * 193;
    float* pbv_s   = bias_vp + 192;

    const int c = blockIdx.x, bh = blockIdx.y;
    const int b = bh >> 3, h = bh & 7;
    const int tid = threadIdx.x;
    const int pbase = (c == 0) ? 127 : 63;

    for (int idx = tid; idx < 64 * 64; idx += 256) {
        int u = idx >> 6, k = idx & 63;
        qv[u * 65 + k] = g_q[((size_t)(R_ + c * 64 + u) * B_ + b) * D_ + h * 64 + k];
    }
    for (int idx = tid; idx < 191 * 64; idx += 256) {
        int pl = idx >> 6, k = idx & 63;
        Pt[k * 193 + pl] = g_pos[(size_t)pl * D_ + h * 64 + k];
    }
    if (tid < 64) pbv_s[tid] = pbv[h * 64 + tid];
    __syncthreads();

    if (tid < 191) {
        float s = 0.f;
        #pragma unroll 8
        for (int k = 0; k < 64; k++) s += pbv_s[k] * Pt[k * 193 + tid];
        bias_vp[tid] = s;
    }
    __syncthreads();

    const int ty = tid >> 4, tx = tid & 15;
    const int plb = pbase - ty + tx;
    float accb[4][8] = {};
    for (int kk = 0; kk < 64; kk++) {
        float qq[4];
        #pragma unroll
        for (int a = 0; a < 4; a++) qq[a] = qv[(ty + 16 * a) * 65 + kk];
        float pv[11];
        #pragma unroll
        for (int t = 0; t < 11; t++) {
            int pl = plb + 16 * (t - 3);
            pl = (pl < 0) ? 0 : (pl > 190 ? 190 : pl);
            pv[t] = Pt[kk * 193 + pl];
        }
        #pragma unroll
        for (int a = 0; a < 4; a++)
            #pragma unroll
            for (int bb = 0; bb < 8; bb++)
                accb[a][bb] += qq[a] * pv[bb - a + 3];
    }
    float* dst = g_bd + ((size_t)bh * 1024 + c * 64) * 128;
    #pragma unroll
    for (int a = 0; a < 4; a++) {
        int u = ty + 16 * a;
        #pragma unroll
        for (int bb = 0; bb < 8; bb++) {
            int j = tx + 16 * bb;
            int pl = pbase - u + j;
            pl = (pl < 0) ? 0 : (pl > 190 ? 190 : pl);
            dst[(size_t)u * 128 + j] = accb[a][bb] + bias_vp[pl];
        }
    }
}

// =====================================================================
// Fused attention (R7 v2 + precomputed bias_u + hi/lo direct output)
// =====================================================================
#define AT_QS  0            // 80 x 65
#define AT_KT  5200         // 64 x 162   (later V: 160 x 64)
#define AT_SS  15568        // 69 x 162
#define AT_BU  26746        // 160
#define AT_FLOATS 26906

__global__ __launch_bounds__(512, 2) void fused_attn_kernel(
    const int* __restrict__ lengths)
{
    extern __shared__ float smf[];
    float* Qs     = smf + AT_QS;
    float* Kt     = smf + AT_KT;
    float* Ss     = smf + AT_SS;
    float* bias_u = smf + AT_BU;

    const int c = blockIdx.x, bh = blockIdx.y;
    const int b = bh >> 3, h = bh & 7;
    const int tid = threadIdx.x;
    const int ustart = (c == 0) ? 0 : (c - 1) * CL_;
    const int n_utt = (c == 0) ? 64 : 128;
    const int ncols = c + 4 + n_utt;
    const int len_b = lengths[b];

    // ---- load Q (80 rows, >=69 zero) ----
    for (int idx = tid; idx < 80 * 64; idx += 512) {
        int r = idx >> 6, k = idx & 63;
        float v = 0.f;
        if (r < 69) {
            int qrow = (r < 4) ? c * 4 + r
                     : (r < 68 ? R_ + c * 64 + (r - 4) : R_ + U_ + c);
            v = g_q[((size_t)qrow * B_ + b) * D_ + h * 64 + k];
        }
        Qs[r * 65 + k] = v;
    }
    // ---- load K transposed [k][i] ----
    for (int idx = tid; idx < 160 * 64; idx += 512) {
        int i = idx >> 6, k = idx & 63;
        float v = 0.f;
        if (i < ncols) {
            int kvrow = kv_row_of(i, c, ustart);
            v = g_kv[((size_t)kvrow * B_ + b) * (2 * D_) + h * 64 + k];
        }
        Kt[k * 162 + i] = v;
    }
    // ---- bias_u from precomputed g_bu ----
    if (tid < 160) {
        float v = 0.f;
        if (tid < ncols)
            v = g_bu[(size_t)bh * 1104 + kv_row_of(tid, c, ustart)];
        bias_u[tid] = v;
    }
    __syncthreads();

    const int ty = tid >> 4, tx = tid & 15;

    // ---- C1: AC scores ----
    {
        int qofs[3];
        #pragma unroll
        for (int a = 0; a < 3; a++) {
            int r = ty + 32 * a; if (r > 79) r = 79;
            qofs[a] = r * 65;
        }
        u64t acc2[3][5] = {};
        for (int kk = 0; kk < 64; kk++) {
            u64t aa[3];
            #pragma unroll
            for (int a = 0; a < 3; a++) aa[a] = pk2(Qs[qofs[a] + kk]);
            u64t bv[5];
            #pragma unroll
            for (int j = 0; j < 5; j++)
                bv[j] = *reinterpret_cast<const u64t*>(&Kt[kk * 162 + 2 * tx + 32 * j]);
            #pragma unroll
            for (int a = 0; a < 3; a++)
                #pragma unroll
                for (int j = 0; j < 5; j++)
                    fma2(acc2[a][j], aa[a], bv[j]);
        }
        #pragma unroll
        for (int a = 0; a < 3; a++) {
            int r = ty + 32 * a;
            if (r < 69) {
                #pragma unroll
                for (int j = 0; j < 5; j++) {
                    int colp = 2 * tx + 32 * j;
                    u64t s = add2(acc2[a][j], *reinterpret_cast<const u64t*>(&bias_u[colp]));
                    *reinterpret_cast<u64t*>(&Ss[r * 162 + colp]) = s;
                }
            }
        }
    }
    __syncthreads();

    // ---- V load into Kt region (stride 64) ----
    float* Vt = Kt;
    for (int idx = tid; idx < ncols * 64; idx += 512) {
        int i = idx >> 6, k = idx & 63;
        int kvrow = kv_row_of(i, c, ustart);
        Vt[i * 64 + k] = g_kv[((size_t)kvrow * B_ + b) * (2 * D_) + D_ + h * 64 + k];
    }

    // ---- softmax (scale + BD + masks) ----
    {
        const int warp = tid >> 5, lane = tid & 31;
        const int limit_j = len_b - ustart;
        const int uc0 = c + 4;
        for (int r = warp; r < 69; r += 16) {
            const bool is_utt = (r >= 4) && (r < 68);
            const float* bd = g_bd + ((size_t)bh * 1024 + c * 64 + (r - 4)) * 128;
            float vals[5];
            float mx = -3.4e38f;
            #pragma unroll
            for (int g = 0; g < 5; g++) {
                int i = lane + 32 * g;
                float v = -3.4e38f;
                if (i < ncols) {
                    float s = Ss[r * 162 + i];
                    if (i >= uc0) {
                        int j = i - uc0;
                        if (is_utt) s += bd[j];
                        v = (j >= limit_j) ? NEG_INF_ : s * SCALING_;
                    } else {
                        v = s * SCALING_;
                    }
                }
                vals[g] = v;
                mx = fmaxf(mx, v);
            }
            #pragma unroll
            for (int o = 16; o > 0; o >>= 1) mx = fmaxf(mx, __shfl_xor_sync(~0u, mx, o));
            float sum = 0.f;
            #pragma unroll
            for (int g = 0; g < 5; g++) {
                float e = __expf(vals[g] - mx);
                vals[g] = e;
                sum += e;
            }
            #pragma unroll
            for (int o = 16; o > 0; o >>= 1) sum += __shfl_xor_sync(~0u, sum, o);
            float inv = 1.f / sum;
            #pragma unroll
            for (int g = 0; g < 5; g++) {
                int i = lane + 32 * g;
                if (i < ncols) Ss[r * 162 + i] = vals[g] * inv;
            }
        }
    }
    __syncthreads();

    // ---- PV; outputs: rows<68 -> bf16 hi/lo (for out-proj), row 68 -> fp32 ----
    {
        u64t acc2[3][2] = {};
        int rofs[3];
        #pragma unroll
        for (int a = 0; a < 3; a++) {
            int rr = ty + 32 * a; if (rr > 68) rr = 68;
            rofs[a] = rr * 162;
        }
        for (int i = 0; i < ncols; i++) {
            u64t ssv[3];
            #pragma unroll
            for (int a = 0; a < 3; a++) ssv[a] = pk2(Ss[rofs[a] + i]);
            u64t vv[2];
            #pragma unroll
            for (int dd = 0; dd < 2; dd++)
                vv[dd] = *reinterpret_cast<const u64t*>(&Vt[i * 64 + 2 * tx + 32 * dd]);
            #pragma unroll
            for (int a = 0; a < 3; a++)
                #pragma unroll
                for (int dd = 0; dd < 2; dd++)
                    fma2(acc2[a][dd], ssv[a], vv[dd]);
        }
        #pragma unroll
        for (int a = 0; a < 3; a++) {
            int r = ty + 32 * a;
            if (r < 68) {
                int qrow = (r < 4) ? c * 4 + r : R_ + c * 64 + (r - 4);
                size_t base = ((size_t)qrow * B_ + b) * 512 + h * 64 + 2 * tx;
                #pragma unroll
                for (int dd = 0; dd < 2; dd++) {
                    float2 v = upk(acc2[a][dd]);
                    __nv_bfloat16 h0 = __float2bfloat16(v.x);
                    __nv_bfloat16 h1 = __float2bfloat16(v.y);
                    __nv_bfloat16 l0 = __float2bfloat16(v.x - __bfloat162float(h0));
                    __nv_bfloat16 l1 = __float2bfloat16(v.y - __bfloat162float(h1));
                    *(uint32_t*)&g_ahi[base + 32 * dd] =
                        (uint32_t)__bfloat16_as_ushort(h0) | ((uint32_t)__bfloat16_as_ushort(h1) << 16);
                    *(uint32_t*)&g_alo[base + 32 * dd] =
                        (uint32_t)__bfloat16_as_ushort(l0) | ((uint32_t)__bfloat16_as_ushort(l1) << 16);
                }
            } else if (r == 68) {
                int qrow = R_ + U_ + c;
                float* dst = g_attn + ((size_t)qrow * B_ + b) * 512 + h * 64 + 2 * tx;
                #pragma unroll
                for (int dd = 0; dd < 2; dd++) {
                    float2 v = upk(acc2[a][dd]);
                    *reinterpret_cast<float2*>(dst + 32 * dd) = v;
                }
            }
        }
    }
}

// ---------------- out_mem = clip(attn[R+U:], -10, 10) ----------------
__global__ void clip_kernel(float* __restrict__ out)
{
    const size_t off = (size_t)(R_ + U_) * B_ * D_;
    int i = blockIdx.x * 256 + threadIdx.x;
    float v = g_attn[off + i];
    out[off + i] = fminf(10.f, fmaxf(-10.f, v));
}

// ---------------- launch ----------------
extern "C" void kernel_launch(void* const* d_in, const int* in_sizes, int n_in,
                              void* d_out, int out_size)
{
    const float* utt    = (const float*)d_in[0];
    const int*   lens   = (const int*)  d_in[1];
    const float* rc     = (const float*)d_in[2];
    const float* summ   = (const float*)d_in[3];
    const float* mem    = (const float*)d_in[4];
    const float* pos_e  = (const float*)d_in[6];
    const float* W_kv   = (const float*)d_in[7];
    const float* b_kv   = (const float*)d_in[8];
    const float* W_q    = (const float*)d_in[9];
    const float* b_q    = (const float*)d_in[10];
    const float* W_out  = (const float*)d_in[11];
    const float* b_out  = (const float*)d_in[12];
    const float* W_pos  = (const float*)d_in[13];
    const float* pbu    = (const float*)d_in[14];
    const float* pbv    = (const float*)d_in[15];
    float* out = (float*)d_out;

    float *pos_buf;
    __nv_bfloat16 *ahi, *alo, *whi;
    cudaGetSymbolAddress((void**)&pos_buf, g_pos);
    cudaGetSymbolAddress((void**)&ahi,     g_ahi);
    cudaGetSymbolAddress((void**)&alo,     g_alo);
    cudaGetSymbolAddress((void**)&whi,     g_whi);
    __nv_bfloat16 *wlo;
    cudaGetSymbolAddress((void**)&wlo,     g_wlo);

    const size_t SMEM_ATTN = (size_t)AT_FLOATS * 4;
    const size_t SMEM_BD   = (size_t)BDSM_FLOATS * 4;
    cudaFuncSetAttribute(fused_attn_kernel,
                         cudaFuncAttributeMaxDynamicSharedMemorySize, (int)SMEM_ATTN);
    cudaFuncSetAttribute(bd_kernel,
                         cudaFuncAttributeMaxDynamicSharedMemorySize, (int)SMEM_BD);
    cudaFuncSetAttribute(gemm_tc_kernel,
                         cudaFuncAttributeMaxDynamicSharedMemorySize, GSM_TOTAL);
    cudaFuncSetAttribute(gemm_qkv_kernel,
                         cudaFuncAttributeMaxDynamicSharedMemorySize, GSM_TOTAL);

    const dim3 blk(256);
    const float* pos_src = pos_e + (size_t)(U_ - 128) * D_;

    // ---- conversions (inputs + all weights) ----
    conv_a_kernel<<<dim3((8952 * 128 + 255) / 256), blk>>>(
        mem, rc, utt, summ, 120, 632, 8824, 8952, 0);
    conv_a_kernel<<<dim3((191 * 128 + 255) / 256), blk>>>(
        pos_src, pos_src, pos_src, pos_src, 191, 191, 191, 191, 8952);
    conv_w_all<<<dim3(2560 * 512 / 256), blk>>>(W_q, W_kv, W_out, W_pos);

    // ---- fused Q+KV projection (N=1536) ----
    gemm_qkv_kernel<<<dim3(12, 70), blk, GSM_TOTAL>>>(b_q, b_kv);

    // ---- pos projection (rows 8952..9142, W_pos region) ----
    gemm_tc_kernel<<<dim3(4, 2), blk, GSM_TOTAL>>>(
        ahi + (size_t)8952 * 512, alo + (size_t)8952 * 512,
        whi + (size_t)2048 * 512, wlo + (size_t)2048 * 512,
        pos_buf, 191, D_, nullptr);

    // ---- attention ----
    bu_kernel<<<dim3(5, 64), blk>>>(pbu);
    bd_kernel<<<dim3(C_, 64), blk, SMEM_BD>>>(pbv);
    fused_attn_kernel<<<dim3(C_, 64), dim3(512), SMEM_ATTN>>>(lens);

    // ---- output projection (attn hi/lo written in-place into g_ahi/g_alo) ----
    gemm_tc_kernel<<<dim3(4, 68), blk, GSM_TOTAL>>>(
        ahi, alo, whi + (size_t)1536 * 512, wlo + (size_t)1536 * 512,
        out, (R_ + U_) * B_, D_, b_out);
    clip_kernel<<<dim3(256), blk>>>(out);
}

// round 11
// speedup vs baseline: 1.2044x; 1.0154x over previous
#include <cuda_runtime.h>
#include <cuda_bf16.h>
#include <cstddef>
#include <cstdint>

// ---------------- problem constants ----------------
#define U_  1024
#define B_  8
#define D_  512
#define H_  8
#define HD_ 64
#define CL_ 64
#define RC_ 4
#define C_  16
#define R_  64
#define S_  16
#define M_  15
#define Q_  1104
#define KV_ 1103
#define NEG_INF_ (-100000000.0f)
#define SCALING_ 0.125f

typedef unsigned long long u64t;

// ---------------- mma / async helpers ----------------
__device__ __forceinline__ uint32_t smem_u32(const void* p) {
    uint32_t a;
    asm("{ .reg .u64 t; cvta.to.shared.u64 t, %1; cvt.u32.u64 %0, t; }" : "=r"(a) : "l"(p));
    return a;
}
#define SWZ128(o) ((o) ^ (((o) >> 3) & 0x70))

__device__ __forceinline__ void ldmx4(uint32_t* r, uint32_t addr) {
    asm volatile("ldmatrix.sync.aligned.m8n8.x4.shared.b16 {%0,%1,%2,%3}, [%4];"
                 : "=r"(r[0]), "=r"(r[1]), "=r"(r[2]), "=r"(r[3]) : "r"(addr));
}
__device__ __forceinline__ void ldmx4t(uint32_t* r, uint32_t addr) {
    asm volatile("ldmatrix.sync.aligned.m8n8.x4.trans.shared.b16 {%0,%1,%2,%3}, [%4];"
                 : "=r"(r[0]), "=r"(r[1]), "=r"(r[2]), "=r"(r[3]) : "r"(addr));
}
__device__ __forceinline__ void mma16816(float* d, const uint32_t* a,
                                         uint32_t b0, uint32_t b1) {
    asm volatile(
        "mma.sync.aligned.m16n8k16.row.col.f32.bf16.bf16.f32 "
        "{%0,%1,%2,%3}, {%4,%5,%6,%7}, {%8,%9}, {%0,%1,%2,%3};"
        : "+f"(d[0]), "+f"(d[1]), "+f"(d[2]), "+f"(d[3])
        : "r"(a[0]), "r"(a[1]), "r"(a[2]), "r"(a[3]), "r"(b0), "r"(b1));
}
__device__ __forceinline__ void cpa16(uint32_t dst, const void* src) {
    asm volatile("cp.async.cg.shared.global [%0], [%1], 16;" :: "r"(dst), "l"(src));
}
#define CPA_COMMIT() asm volatile("cp.async.commit_group;" ::: "memory")
#define CPA_WAIT1()  asm volatile("cp.async.wait_group 1;" ::: "memory")
#define CPA_WAIT0()  asm volatile("cp.async.wait_group 0;" ::: "memory")

// pack two floats into bf16x2 hi and lo words
__device__ __forceinline__ void pack_hl(float x, float y, uint32_t& hi, uint32_t& lo) {
    __nv_bfloat16 h0 = __float2bfloat16(x), h1 = __float2bfloat16(y);
    __nv_bfloat16 l0 = __float2bfloat16(x - __bfloat162float(h0));
    __nv_bfloat16 l1 = __float2bfloat16(y - __bfloat162float(h1));
    hi = (uint32_t)__bfloat16_as_ushort(h0) | ((uint32_t)__bfloat16_as_ushort(h1) << 16);
    lo = (uint32_t)__bfloat16_as_ushort(l0) | ((uint32_t)__bfloat16_as_ushort(l1) << 16);
}

// ---------------- scratch (device globals; no allocs) ----------------
__device__ float g_q[(size_t)Q_ * B_ * D_];
__device__ float g_kv[(size_t)KV_ * B_ * 2 * D_];
__device__ float g_pos[(size_t)192 * D_];
__device__ float g_attn[(size_t)Q_ * B_ * D_];
__device__ float g_bd[(size_t)64 * 1024 * 128];
__device__ float g_bu[(size_t)64 * 1104];
// weights: W_q 0..511 | W_kv 512..1535 | W_out 1536..2047 | W_pos 2048..2559
__device__ __nv_bfloat16 g_whi[(size_t)2560 * 512];
__device__ __nv_bfloat16 g_wlo[(size_t)2560 * 512];
// A concat: [mem|rc|utt|summ|pos]; rows 0..8703 overwritten by attention output
__device__ __nv_bfloat16 g_ahi[(size_t)9216 * 512];
__device__ __nv_bfloat16 g_alo[(size_t)9216 * 512];

__device__ __forceinline__ int kv_row_of(int i, int c, int ustart) {
    return (i < c) ? i
         : (i < c + 4 ? M_ + c * 4 + (i - c)
                      : M_ + R_ + ustart + (i - c - 4));
}

// =====================================================================
// All-weights split
// =====================================================================
__global__ void conv_w_all(const float* __restrict__ Wq, const float* __restrict__ Wkv,
                           const float* __restrict__ Wout, const float* __restrict__ Wpos)
{
    int i = blockIdx.x * 256 + threadIdx.x;
    int row = i >> 9, col = i & 511;
    const float* src; int lr;
    if (row < 512)       { src = Wq;   lr = row; }
    else if (row < 1536) { src = Wkv;  lr = row - 512; }
    else if (row < 2048) { src = Wout; lr = row - 1536; }
    else                 { src = Wpos; lr = row - 2048; }
    float a = src[(size_t)lr * 512 + col];
    __nv_bfloat16 h = __float2bfloat16(a);
    g_whi[i] = h;
    g_wlo[i] = __float2bfloat16(a - __bfloat162float(h));
}

// =====================================================================
// A split (concat of <=4 row segments)
// =====================================================================
__global__ void conv_a_kernel(const float* __restrict__ A0, const float* __restrict__ A1,
                              const float* __restrict__ A2, const float* __restrict__ A3,
                              int r1, int r2, int r3, int nrows, int dst_row0)
{
    int i = blockIdx.x * 256 + threadIdx.x;
    if (i >= nrows * 128) return;
    int row = i >> 7, c4 = (i & 127) * 4;
    const float* src; int lr;
    if (row < r1)      { src = A0; lr = row; }
    else if (row < r2) { src = A1; lr = row - r1; }
    else if (row < r3) { src = A2; lr = row - r2; }
    else               { src = A3; lr = row - r3; }
    float4 v = *(const float4*)(src + (size_t)lr * 512 + c4);
    uint32_t h0, l0, h1, l1;
    pack_hl(v.x, v.y, h0, l0);
    pack_hl(v.z, v.w, h1, l1);
    size_t o = (size_t)(dst_row0 + row) * 512 + c4;
    *(uint2*)&g_ahi[o] = make_uint2(h0, h1);
    *(uint2*)&g_alo[o] = make_uint2(l0, l1);
}

// =====================================================================
// GEMM mainloop: 128x128 tile, cp.async 3-stage, 24 chunks
// =====================================================================
#define GSM_TOTAL 98304

#define GEMM_MAINLOOP(AHI, ALO, WHI, WLO, MRTOT)                                    \
    float acc[2][8][4] = {};                                                        \
    {                                                                               \
        auto issue = [&](int cc) {                                                  \
            const int seg = cc >> 3;                                                \
            const int k0 = (cc & 7) * 64;                                           \
            const __nv_bfloat16* asrc = (seg == 1) ? (ALO) : (AHI);                 \
            const __nv_bfloat16* wsrc = (seg == 2) ? (WLO) : (WHI);                 \
            char* abuf = gsm + (cc % 3) * 16384;                                    \
            char* bbuf = gsm + 49152 + (cc % 3) * 16384;                            \
            _Pragma("unroll")                                                       \
            for (int t = 0; t < 4; t++) {                                           \
                int ar = car + t * 32;                                              \
                int gr = row0 + ar; if (gr >= (MRTOT)) gr = (MRTOT) - 1;            \
                cpa16(smem_u32(abuf) + SWZ128((uint32_t)(ar * 128 + cg8 * 16)),     \
                      asrc + (size_t)gr * 512 + k0 + cg8 * 8);                      \
            }                                                                       \
            _Pragma("unroll")                                                       \
            for (int t = 0; t < 4; t++) {                                           \
                int br = car + t * 32;                                              \
                cpa16(smem_u32(bbuf) + SWZ128((uint32_t)(br * 128 + cg8 * 16)),     \
                      wsrc + (size_t)(col0 + br) * 512 + k0 + cg8 * 8);             \
            }                                                                       \
            CPA_COMMIT();                                                           \
        };                                                                          \
        issue(0);                                                                   \
        issue(1);                                                                   \
        const int l15 = lane & 15, lh = lane >> 4;                                  \
        const int l8 = lane & 7, lg = lane >> 3;                                    \
        for (int cc = 0; cc < 24; cc++) {                                           \
            if (cc < 23) CPA_WAIT1(); else CPA_WAIT0();                             \
            __syncthreads();                                                        \
            const uint32_t Ab = sb + (cc % 3) * 16384;                              \
            const uint32_t Bb = sb + 49152 + (cc % 3) * 16384;                      \
            _Pragma("unroll")                                                       \
            for (int s = 0; s < 4; s++) {                                           \
                uint32_t afr[2][4];                                                 \
                _Pragma("unroll")                                                   \
                for (int mt = 0; mt < 2; mt++) {                                    \
                    int r = wm * 32 + mt * 16 + l15;                                \
                    ldmx4(afr[mt], Ab + SWZ128((uint32_t)(r * 128 + s * 32 + lh * 16))); \
                }                                                                   \
                uint32_t bfr[4][4];                                                 \
                _Pragma("unroll")                                                   \
                for (int bt = 0; bt < 4; bt++) {                                    \
                    int n = wn * 64 + bt * 16 + ((lg >> 1) ? 8 : 0) + l8;           \
                    ldmx4(bfr[bt], Bb + SWZ128((uint32_t)(n * 128 + s * 32 + (lg & 1) * 16))); \
                }                                                                   \
                _Pragma("unroll")                                                   \
                for (int mt = 0; mt < 2; mt++)                                      \
                    _Pragma("unroll")                                               \
                    for (int nt = 0; nt < 8; nt++) {                                \
                        int bt = nt >> 1, sub = nt & 1;                             \
                        mma16816(acc[mt][nt], afr[mt], bfr[bt][2*sub], bfr[bt][2*sub+1]); \
                    }                                                               \
            }                                                                       \
            if (cc + 2 < 24) issue(cc + 2);                                         \
        }                                                                           \
    }

// ---- generic GEMM (pos / out projections) ----
__global__ __launch_bounds__(256, 2) void gemm_tc_kernel(
    const __nv_bfloat16* __restrict__ Ahi, const __nv_bfloat16* __restrict__ Alo,
    const __nv_bfloat16* __restrict__ Whib, const __nv_bfloat16* __restrict__ Wlob,
    float* __restrict__ Cm, int Mr, int ldc, const float* __restrict__ bias)
{
    extern __shared__ char gsm[];
    const uint32_t sb = smem_u32(gsm);
    const int tid = threadIdx.x;
    const int wid = tid >> 5, lane = tid & 31;
    const int wm = wid & 3, wn = wid >> 2;
    const int row0 = blockIdx.y * 128, col0 = blockIdx.x * 128;
    const int car = tid >> 3, cg8 = tid & 7;

    GEMM_MAINLOOP(Ahi, Alo, Whib, Wlob, Mr)

    const int quad = lane >> 2, tq = lane & 3;
    #pragma unroll
    for (int mt = 0; mt < 2; mt++) {
        #pragma unroll
        for (int nt = 0; nt < 8; nt++) {
            int gr0 = row0 + wm * 32 + mt * 16 + quad;
            int gc  = col0 + wn * 64 + nt * 8 + tq * 2;
            float b0 = bias ? bias[gc]     : 0.f;
            float b1 = bias ? bias[gc + 1] : 0.f;
            #pragma unroll
            for (int half = 0; half < 2; half++) {
                int gr = gr0 + half * 8;
                if (gr < Mr) {
                    float2 v = {acc[mt][nt][half*2+0] + b0, acc[mt][nt][half*2+1] + b1};
                    *(float2*)&Cm[(size_t)gr * ldc + gc] = v;
                }
            }
        }
    }
}

// ---- fused Q+KV GEMM ----
__global__ __launch_bounds__(256, 2) void gemm_qkv_kernel(
    const float* __restrict__ b_q, const float* __restrict__ b_kv)
{
    extern __shared__ char gsm[];
    const uint32_t sb = smem_u32(gsm);
    const int tid = threadIdx.x;
    const int wid = tid >> 5, lane = tid & 31;
    const int wm = wid & 3, wn = wid >> 2;
    const int row0 = blockIdx.y * 128, col0 = blockIdx.x * 128;
    const int car = tid >> 3, cg8 = tid & 7;

    GEMM_MAINLOOP(g_ahi, g_alo, g_whi, g_wlo, 8952)

    const int quad = lane >> 2, tq = lane & 3;
    const bool is_q = (col0 < 512);
    #pragma unroll
    for (int mt = 0; mt < 2; mt++) {
        #pragma unroll
        for (int nt = 0; nt < 8; nt++) {
            int gr0 = row0 + wm * 32 + mt * 16 + quad;
            int gc  = col0 + wn * 64 + nt * 8 + tq * 2;
            #pragma unroll
            for (int half = 0; half < 2; half++) {
                int gr = gr0 + half * 8;
                if (gr >= 8952) continue;
                float2 v = {acc[mt][nt][half*2+0], acc[mt][nt][half*2+1]};
                if (is_q) {
                    int qr = gr - 120;
                    if (qr >= 0) {
                        v.x += b_q[gc]; v.y += b_q[gc + 1];
                        *(float2*)&g_q[(size_t)qr * 512 + gc] = v;
                    }
                } else {
                    int kc = gc - 512;
                    if (gr < 8824) {
                        v.x += b_kv[kc]; v.y += b_kv[kc + 1];
                        *(float2*)&g_kv[(size_t)gr * 1024 + kc] = v;
                    }
                }
            }
        }
    }
}

// =====================================================================
// bu kernel
// =====================================================================
__global__ void bu_kernel(const float* __restrict__ pbu)
{
    const int bh = blockIdx.y;
    const int b = bh >> 3, h = bh & 7;
    int i = blockIdx.x * 256 + threadIdx.x;
    if (i >= KV_) return;
    const float4* kp = (const float4*)(g_kv + ((size_t)i * B_ + b) * 1024 + h * 64);
    const float4* pp = (const float4*)(pbu + h * 64);
    float s = 0.f;
    #pragma unroll 4
    for (int k4 = 0; k4 < 16; k4++) {
        float4 kvv = kp[k4];
        float4 pv = pp[k4];
        s += pv.x * kvv.x + pv.y * kvv.y + pv.z * kvv.z + pv.w * kvv.w;
    }
    g_bu[(size_t)bh * 1104 + i] = s;
}

// =====================================================================
// BD kernel (unchanged)
// =====================================================================
#define BDSM_FLOATS (64*65 + 64*193 + 192 + 64)

__global__ __launch_bounds__(256) void bd_kernel(const float* __restrict__ pbv)
{
    extern __shared__ float smf[];
    float* qv      = smf;
    float* Pt      = smf + 64 * 65;
    float* bias_vp = Pt + 64 * 193;
    float* pbv_s   = bias_vp + 192;

    const int c = blockIdx.x, bh = blockIdx.y;
    const int b = bh >> 3, h = bh & 7;
    const int tid = threadIdx.x;
    const int pbase = (c == 0) ? 127 : 63;

    for (int idx = tid; idx < 64 * 64; idx += 256) {
        int u = idx >> 6, k = idx & 63;
        qv[u * 65 + k] = g_q[((size_t)(R_ + c * 64 + u) * B_ + b) * D_ + h * 64 + k];
    }
    for (int idx = tid; idx < 191 * 64; idx += 256) {
        int pl = idx >> 6, k = idx & 63;
        Pt[k * 193 + pl] = g_pos[(size_t)pl * D_ + h * 64 + k];
    }
    if (tid < 64) pbv_s[tid] = pbv[h * 64 + tid];
    __syncthreads();

    if (tid < 191) {
        float s = 0.f;
        #pragma unroll 8
        for (int k = 0; k < 64; k++) s += pbv_s[k] * Pt[k * 193 + tid];
        bias_vp[tid] = s;
    }
    __syncthreads();

    const int ty = tid >> 4, tx = tid & 15;
    const int plb = pbase - ty + tx;
    float accb[4][8] = {};
    for (int kk = 0; kk < 64; kk++) {
        float qq[4];
        #pragma unroll
        for (int a = 0; a < 4; a++) qq[a] = qv[(ty + 16 * a) * 65 + kk];
        float pv[11];
        #pragma unroll
        for (int t = 0; t < 11; t++) {
            int pl = plb + 16 * (t - 3);
            pl = (pl < 0) ? 0 : (pl > 190 ? 190 : pl);
            pv[t] = Pt[kk * 193 + pl];
        }
        #pragma unroll
        for (int a = 0; a < 4; a++)
            #pragma unroll
            for (int bb = 0; bb < 8; bb++)
                accb[a][bb] += qq[a] * pv[bb - a + 3];
    }
    float* dst = g_bd + ((size_t)bh * 1024 + c * 64) * 128;
    #pragma unroll
    for (int a = 0; a < 4; a++) {
        int u = ty + 16 * a;
        #pragma unroll
        for (int bb = 0; bb < 8; bb++) {
            int j = tx + 16 * bb;
            int pl = pbase - u + j;
            pl = (pl < 0) ? 0 : (pl > 190 ? 190 : pl);
            dst[(size_t)u * 128 + j] = accb[a][bb] + bias_vp[pl];
        }
    }
}

// =====================================================================
// Fused attention v4: in-kernel bf16 conversion + HMMA C1/PV.
// 512 threads, ~113KB smem, 1 CTA/SM (16 warps).
// smem: QHI 0 (80x128B) QLO 10240 | KHI 20480 (160x128B) KLO 40960 (V reuses)
//       UN 61440: scores fp32 stride 648B (80 rows) then P hi(336B-stride)+lo
//       BU 115200 (160 f)
// =====================================================================
#define FZ_QHI 0
#define FZ_QLO 10240
#define FZ_KHI 20480
#define FZ_KLO 40960
#define FZ_UN  61440
#define FZ_PLO (FZ_UN + 26880)
#define FZ_BU  (FZ_UN + 53760)
#define FZ_TOTAL (FZ_BU + 640)

__global__ __launch_bounds__(512) void fused_attn_kernel(
    const int* __restrict__ lengths)
{
    extern __shared__ char fsm[];
    const uint32_t sb = smem_u32(fsm);
    float* bias_u = (float*)(fsm + FZ_BU);

    const int c = blockIdx.x, bh = blockIdx.y;
    const int b = bh >> 3, h = bh & 7;
    const int tid = threadIdx.x;
    const int wid = tid >> 5, lane = tid & 31;
    const int ustart = (c == 0) ? 0 : (c - 1) * CL_;
    const int ncols = c + 4 + ((c == 0) ? 64 : 128);
    const int len_b = lengths[b];

    // ---- convert Q (80 rows) fp32 -> bf16 hi/lo SW128 smem ----
    for (int idx = tid; idx < 80 * 32; idx += 512) {
        int r = idx >> 5, pr = idx & 31;
        uint32_t vhi = 0, vlo = 0;
        if (r < 69) {
            int qrow = (r < 4) ? c * 4 + r
                     : (r < 68 ? R_ + c * 64 + (r - 4) : R_ + U_ + c);
            float2 v = *(const float2*)(g_q + ((size_t)qrow * B_ + b) * 512 + h * 64 + pr * 2);
            pack_hl(v.x, v.y, vhi, vlo);
        }
        uint32_t off = SWZ128((uint32_t)(r * 128 + pr * 4));
        *(uint32_t*)(fsm + FZ_QHI + off) = vhi;
        *(uint32_t*)(fsm + FZ_QLO + off) = vlo;
    }
    // ---- convert K (160 rows) ----
    for (int idx = tid; idx < 160 * 32; idx += 512) {
        int r = idx >> 5, pr = idx & 31;
        uint32_t vhi = 0, vlo = 0;
        if (r < ncols) {
            int kvrow = kv_row_of(r, c, ustart);
            float2 v = *(const float2*)(g_kv + ((size_t)kvrow * B_ + b) * 1024 + h * 64 + pr * 2);
            pack_hl(v.x, v.y, vhi, vlo);
        }
        uint32_t off = SWZ128((uint32_t)(r * 128 + pr * 4));
        *(uint32_t*)(fsm + FZ_KHI + off) = vhi;
        *(uint32_t*)(fsm + FZ_KLO + off) = vlo;
    }
    if (tid < 160)
        bias_u[tid] = (tid < ncols) ? g_bu[(size_t)bh * 1104 + kv_row_of(tid, c, ustart)] : 0.f;
    __syncthreads();

    const int l15 = lane & 15, lh = lane >> 4;
    const int l8 = lane & 7, lg = lane >> 3;
    const int quad = lane >> 2, tq = lane & 3;

    // ---- C1: scores = Q.K^T (HMMA, 3 passes). warps: wmc(0..4) x wnc(0..2) ----
    {
        const int wmc = wid / 3, wnc = wid % 3;   // wid 15 -> wmc 5 inactive
        if (wmc < 5) {
            float acc[4][2][4] = {};
            #pragma unroll
            for (int pass = 0; pass < 3; pass++) {
                const uint32_t Ab = sb + ((pass == 1) ? FZ_QLO : FZ_QHI);
                const uint32_t Bb = sb + ((pass == 2) ? FZ_KLO : FZ_KHI);
                #pragma unroll
                for (int s = 0; s < 4; s++) {
                    uint32_t afr[4];
                    ldmx4(afr, Ab + SWZ128((uint32_t)((wmc * 16 + l15) * 128 + s * 32 + lh * 16)));
                    #pragma unroll
                    for (int nj = 0; nj < 4; nj++) {
                        int nt = wnc + 3 * nj;
                        if (nt < 10) {
                            uint32_t bfr[4];
                            int n = nt * 16 + ((lg >> 1) ? 8 : 0) + l8;
                            ldmx4(bfr, Bb + SWZ128((uint32_t)(n * 128 + s * 32 + (lg & 1) * 16)));
                            mma16816(acc[nj][0], afr, bfr[0], bfr[1]);
                            mma16816(acc[nj][1], afr, bfr[2], bfr[3]);
                        }
                    }
                }
            }
            // store scores fp32, stride 648B
            #pragma unroll
            for (int nj = 0; nj < 4; nj++) {
                int nt = wnc + 3 * nj;
                if (nt < 10) {
                    int r0 = wmc * 16 + quad;
                    #pragma unroll
                    for (int hf = 0; hf < 2; hf++) {
                        int col = nt * 16 + hf * 8 + tq * 2;
                        *(float2*)(fsm + FZ_UN + (size_t)r0 * 648 + col * 4) =
                            make_float2(acc[nj][hf][0], acc[nj][hf][1]);
                        *(float2*)(fsm + FZ_UN + (size_t)(r0 + 8) * 648 + col * 4) =
                            make_float2(acc[nj][hf][2], acc[nj][hf][3]);
                    }
                }
            }
        }
    }
    __syncthreads();

    // ---- V conversion (overwrites K region) + softmax phase A (reads scores) ----
    float pvals[5][5];
    {
        for (int idx = tid; idx < 160 * 32; idx += 512) {
            int r = idx >> 5, pr = idx & 31;
            uint32_t vhi = 0, vlo = 0;
            if (r < ncols) {
                int kvrow = kv_row_of(r, c, ustart);
                float2 v = *(const float2*)(g_kv + ((size_t)kvrow * B_ + b) * 1024 + 512 + h * 64 + pr * 2);
                pack_hl(v.x, v.y, vhi, vlo);
            }
            uint32_t off = SWZ128((uint32_t)(r * 128 + pr * 4));
            *(uint32_t*)(fsm + FZ_KHI + off) = vhi;
            *(uint32_t*)(fsm + FZ_KLO + off) = vlo;
        }
        const int limit_j = len_b - ustart;
        const int uc0 = c + 4;
        int slot = 0;
        for (int r = wid; r < 69; r += 16, slot++) {
            const bool is_utt = (r >= 4) && (r < 68);
            const float* bdrow = g_bd + ((size_t)bh * 1024 + c * 64 + (r - 4)) * 128;
            float vals[5];
            float mx = -3.4e38f;
            #pragma unroll
            for (int g = 0; g < 5; g++) {
                int i = lane + 32 * g;
                float v = -3.4e38f;
                if (i < ncols) {
                    float s = *(const float*)(fsm + FZ_UN + (size_t)r * 648 + i * 4) + bias_u[i];
                    if (i >= uc0) {
                        int j = i - uc0;
                        if (is_utt) s += bdrow[j];
                        v = (j >= limit_j) ? NEG_INF_ : s * SCALING_;
                    } else {
                        v = s * SCALING_;
                    }
                }
                vals[g] = v;
                mx = fmaxf(mx, v);
            }
            #pragma unroll
            for (int o = 16; o > 0; o >>= 1) mx = fmaxf(mx, __shfl_xor_sync(~0u, mx, o));
            float sum = 0.f;
            #pragma unroll
            for (int g = 0; g < 5; g++) {
                float e = __expf(vals[g] - mx);
                vals[g] = e;
                sum += e;
            }
            #pragma unroll
            for (int o = 16; o > 0; o >>= 1) sum += __shfl_xor_sync(~0u, sum, o);
            float inv = 1.f / sum;
            #pragma unroll
            for (int g = 0; g < 5; g++) pvals[slot][g] = vals[g] * inv;
        }
    }
    __syncthreads();

    // ---- phase B: write P bf16 hi/lo (stride 336B) over score region + zero pads ----
    {
        int slot = 0;
        for (int r = wid; r < 69; r += 16, slot++) {
            #pragma unroll
            for (int g = 0; g < 5; g++) {
                int i = lane + 32 * g;
                float p = pvals[slot][g];
                __nv_bfloat16 hp = __float2bfloat16(p);
                __nv_bfloat16 lp = __float2bfloat16(p - __bfloat162float(hp));
                *(ushort*)(fsm + FZ_UN + r * 336 + i * 2) = __bfloat16_as_ushort(hp);
                *(ushort*)(fsm + FZ_PLO + r * 336 + i * 2) = __bfloat16_as_ushort(lp);
            }
        }
        // zero P rows 69..79 (3696 bytes each buffer)
        for (int idx = tid; idx < 462; idx += 512) {
            *(u64t*)(fsm + FZ_UN + 23184 + idx * 8) = 0ull;
            *(u64t*)(fsm + FZ_PLO + 23184 + idx * 8) = 0ull;
        }
    }
    __syncthreads();

    // ---- PV: out = P.V (HMMA, 3 passes). warps: wmp(0..3) x wnp(0..3), mi<2 ----
    {
        const int wmp = wid >> 2, wnp = wid & 3;
        float accp[2][2][4] = {};
        #pragma unroll
        for (int pass = 0; pass < 3; pass++) {
            const uint32_t Ab = sb + ((pass == 1) ? FZ_PLO : FZ_UN);
            const uint32_t Bb = sb + ((pass == 2) ? FZ_KLO : FZ_KHI);
            #pragma unroll
            for (int kk = 0; kk < 10; kk++) {
                uint32_t bfr[4];
                ldmx4t(bfr, Bb + SWZ128((uint32_t)((kk * 16 + l15) * 128 + wnp * 32 + lh * 16)));
                #pragma unroll
                for (int mi = 0; mi < 2; mi++) {
                    int m = wmp + 4 * mi;
                    if (m < 5) {
                        uint32_t afr[4];
                        ldmx4(afr, Ab + (uint32_t)((m * 16 + l15) * 336 + kk * 32 + lh * 16));
                        mma16816(accp[mi][0], afr, bfr[0], bfr[1]);
                        mma16816(accp[mi][1], afr, bfr[2], bfr[3]);
                    }
                }
            }
        }
        #pragma unroll
        for (int mi = 0; mi < 2; mi++) {
            int m = wmp + 4 * mi;
            if (m >= 5) continue;
            int r0 = m * 16 + quad;
            #pragma unroll
            for (int hf = 0; hf < 2; hf++) {
                int r = r0 + hf * 8;
                if (r < 68) {
                    int qrow = (r < 4) ? c * 4 + r : R_ + c * 64 + (r - 4);
                    size_t base = ((size_t)qrow * B_ + b) * 512 + h * 64;
                    #pragma unroll
                    for (int n = 0; n < 2; n++) {
                        int d = wnp * 16 + n * 8 + tq * 2;
                        uint32_t vhi, vlo;
                        pack_hl(accp[mi][n][hf*2+0], accp[mi][n][hf*2+1], vhi, vlo);
                        *(uint32_t*)&g_ahi[base + d] = vhi;
                        *(uint32_t*)&g_alo[base + d] = vlo;
                    }
                } else if (r == 68) {
                    int qrow = R_ + U_ + c;
                    float* dst = g_attn + ((size_t)qrow * B_ + b) * 512 + h * 64;
                    #pragma unroll
                    for (int n = 0; n < 2; n++) {
                        int d = wnp * 16 + n * 8 + tq * 2;
                        *(float2*)(dst + d) =
                            make_float2(accp[mi][n][hf*2+0], accp[mi][n][hf*2+1]);
                    }
                }
            }
        }
    }
}

// ---------------- out_mem = clip(attn[R+U:], -10, 10) ----------------
__global__ void clip_kernel(float* __restrict__ out)
{
    const size_t off = (size_t)(R_ + U_) * B_ * D_;
    int i = blockIdx.x * 256 + threadIdx.x;
    float v = g_attn[off + i];
    out[off + i] = fminf(10.f, fmaxf(-10.f, v));
}

// ---------------- launch ----------------
extern "C" void kernel_launch(void* const* d_in, const int* in_sizes, int n_in,
                              void* d_out, int out_size)
{
    const float* utt    = (const float*)d_in[0];
    const int*   lens   = (const int*)  d_in[1];
    const float* rc     = (const float*)d_in[2];
    const float* summ   = (const float*)d_in[3];
    const float* mem    = (const float*)d_in[4];
    const float* pos_e  = (const float*)d_in[6];
    const float* W_kv   = (const float*)d_in[7];
    const float* b_kv   = (const float*)d_in[8];
    const float* W_q    = (const float*)d_in[9];
    const float* b_q    = (const float*)d_in[10];
    const float* W_out  = (const float*)d_in[11];
    const float* b_out  = (const float*)d_in[12];
    const float* W_pos  = (const float*)d_in[13];
    const float* pbu    = (const float*)d_in[14];
    const float* pbv    = (const float*)d_in[15];
    float* out = (float*)d_out;

    float *pos_buf;
    __nv_bfloat16 *ahi, *alo, *whi, *wlo;
    cudaGetSymbolAddress((void**)&pos_buf, g_pos);
    cudaGetSymbolAddress((void**)&ahi,     g_ahi);
    cudaGetSymbolAddress((void**)&alo,     g_alo);
    cudaGetSymbolAddress((void**)&whi,     g_whi);
    cudaGetSymbolAddress((void**)&wlo,     g_wlo);

    const size_t SMEM_BD = (size_t)BDSM_FLOATS * 4;
    cudaFuncSetAttribute(fused_attn_kernel,
                         cudaFuncAttributeMaxDynamicSharedMemorySize, FZ_TOTAL);
    cudaFuncSetAttribute(bd_kernel,
                         cudaFuncAttributeMaxDynamicSharedMemorySize, (int)SMEM_BD);
    cudaFuncSetAttribute(gemm_tc_kernel,
                         cudaFuncAttributeMaxDynamicSharedMemorySize, GSM_TOTAL);
    cudaFuncSetAttribute(gemm_qkv_kernel,
                         cudaFuncAttributeMaxDynamicSharedMemorySize, GSM_TOTAL);

    const dim3 blk(256);
    const float* pos_src = pos_e + (size_t)(U_ - 128) * D_;

    // ---- conversions ----
    conv_a_kernel<<<dim3((8952 * 128 + 255) / 256), blk>>>(
        mem, rc, utt, summ, 120, 632, 8824, 8952, 0);
    conv_a_kernel<<<dim3((191 * 128 + 255) / 256), blk>>>(
        pos_src, pos_src, pos_src, pos_src, 191, 191, 191, 191, 8952);
    conv_w_all<<<dim3(2560 * 512 / 256), blk>>>(W_q, W_kv, W_out, W_pos);

    // ---- fused Q+KV projection ----
    gemm_qkv_kernel<<<dim3(12, 70), blk, GSM_TOTAL>>>(b_q, b_kv);

    // ---- pos projection ----
    gemm_tc_kernel<<<dim3(4, 2), blk, GSM_TOTAL>>>(
        ahi + (size_t)8952 * 512, alo + (size_t)8952 * 512,
        whi + (size_t)2048 * 512, wlo + (size_t)2048 * 512,
        pos_buf, 191, D_, nullptr);

    // ---- attention ----
    bu_kernel<<<dim3(5, 64), blk>>>(pbu);
    bd_kernel<<<dim3(C_, 64), blk, SMEM_BD>>>(pbv);
    fused_attn_kernel<<<dim3(C_, 64), dim3(512), FZ_TOTAL>>>(lens);

    // ---- output projection ----
    gemm_tc_kernel<<<dim3(4, 68), blk, GSM_TOTAL>>>(
        ahi, alo, whi + (size_t)1536 * 512, wlo + (size_t)1536 * 512,
        out, (R_ + U_) * B_, D_, b_out);
    clip_kernel<<<dim3(256), blk>>>(out);
}

// round 12
// speedup vs baseline: 1.4092x; 1.1701x over previous
#include <cuda_runtime.h>
#include <cuda_bf16.h>
#include <cstddef>
#include <cstdint>

// ---------------- problem constants ----------------
#define U_  1024
#define B_  8
#define D_  512
#define H_  8
#define HD_ 64
#define CL_ 64
#define RC_ 4
#define C_  16
#define R_  64
#define S_  16
#define M_  15
#define Q_  1104
#define KV_ 1103
#define NEG_INF_ (-100000000.0f)
#define SCALING_ 0.125f

typedef unsigned long long u64t;

// ---------------- mma / async helpers ----------------
__device__ __forceinline__ uint32_t smem_u32(const void* p) {
    uint32_t a;
    asm("{ .reg .u64 t; cvta.to.shared.u64 t, %1; cvt.u32.u64 %0, t; }" : "=r"(a) : "l"(p));
    return a;
}
#define SWZ128(o) ((o) ^ (((o) >> 3) & 0x70))

__device__ __forceinline__ void ldmx4(uint32_t* r, uint32_t addr) {
    asm volatile("ldmatrix.sync.aligned.m8n8.x4.shared.b16 {%0,%1,%2,%3}, [%4];"
                 : "=r"(r[0]), "=r"(r[1]), "=r"(r[2]), "=r"(r[3]) : "r"(addr));
}
__device__ __forceinline__ void ldmx4t(uint32_t* r, uint32_t addr) {
    asm volatile("ldmatrix.sync.aligned.m8n8.x4.trans.shared.b16 {%0,%1,%2,%3}, [%4];"
                 : "=r"(r[0]), "=r"(r[1]), "=r"(r[2]), "=r"(r[3]) : "r"(addr));
}
__device__ __forceinline__ void mma16816(float* d, const uint32_t* a,
                                         uint32_t b0, uint32_t b1) {
    asm volatile(
        "mma.sync.aligned.m16n8k16.row.col.f32.bf16.bf16.f32 "
        "{%0,%1,%2,%3}, {%4,%5,%6,%7}, {%8,%9}, {%0,%1,%2,%3};"
        : "+f"(d[0]), "+f"(d[1]), "+f"(d[2]), "+f"(d[3])
        : "r"(a[0]), "r"(a[1]), "r"(a[2]), "r"(a[3]), "r"(b0), "r"(b1));
}
__device__ __forceinline__ void cpa16(uint32_t dst, const void* src) {
    asm volatile("cp.async.cg.shared.global [%0], [%1], 16;" :: "r"(dst), "l"(src));
}
#define CPA_COMMIT() asm volatile("cp.async.commit_group;" ::: "memory")
#define CPA_WAIT1()  asm volatile("cp.async.wait_group 1;" ::: "memory")
#define CPA_WAIT0()  asm volatile("cp.async.wait_group 0;" ::: "memory")

// pack two floats into bf16x2 hi and lo words
__device__ __forceinline__ void pack_hl(float x, float y, uint32_t& hi, uint32_t& lo) {
    __nv_bfloat16 h0 = __float2bfloat16(x), h1 = __float2bfloat16(y);
    __nv_bfloat16 l0 = __float2bfloat16(x - __bfloat162float(h0));
    __nv_bfloat16 l1 = __float2bfloat16(y - __bfloat162float(h1));
    hi = (uint32_t)__bfloat16_as_ushort(h0) | ((uint32_t)__bfloat16_as_ushort(h1) << 16);
    lo = (uint32_t)__bfloat16_as_ushort(l0) | ((uint32_t)__bfloat16_as_ushort(l1) << 16);
}

// ---------------- scratch (device globals; no allocs) ----------------
__device__ float g_q[(size_t)Q_ * B_ * D_];
__device__ float g_kv[(size_t)KV_ * B_ * 2 * D_];
__device__ float g_pos[(size_t)192 * D_];
__device__ float g_attn[(size_t)Q_ * B_ * D_];
__device__ float g_bu[(size_t)64 * 1104];
__device__ float g_bvp[8 * 192];
// weights: W_q 0..511 | W_kv 512..1535 | W_out 1536..2047 | W_pos 2048..2559
__device__ __nv_bfloat16 g_whi[(size_t)2560 * 512];
__device__ __nv_bfloat16 g_wlo[(size_t)2560 * 512];
// A concat: [mem|rc|utt|summ|pos]; rows 0..8703 overwritten by attention output
__device__ __nv_bfloat16 g_ahi[(size_t)9216 * 512];
__device__ __nv_bfloat16 g_alo[(size_t)9216 * 512];
__device__ __nv_bfloat16 g_poshi[(size_t)192 * 512];
__device__ __nv_bfloat16 g_poslo[(size_t)192 * 512];

__device__ __forceinline__ int kv_row_of(int i, int c, int ustart) {
    return (i < c) ? i
         : (i < c + 4 ? M_ + c * 4 + (i - c)
                      : M_ + R_ + ustart + (i - c - 4));
}

// =====================================================================
// All-weights split
// =====================================================================
__global__ void conv_w_all(const float* __restrict__ Wq, const float* __restrict__ Wkv,
                           const float* __restrict__ Wout, const float* __restrict__ Wpos)
{
    int i = blockIdx.x * 256 + threadIdx.x;
    int row = i >> 9, col = i & 511;
    const float* src; int lr;
    if (row < 512)       { src = Wq;   lr = row; }
    else if (row < 1536) { src = Wkv;  lr = row - 512; }
    else if (row < 2048) { src = Wout; lr = row - 1536; }
    else                 { src = Wpos; lr = row - 2048; }
    float a = src[(size_t)lr * 512 + col];
    __nv_bfloat16 h = __float2bfloat16(a);
    g_whi[i] = h;
    g_wlo[i] = __float2bfloat16(a - __bfloat162float(h));
}

// =====================================================================
// A split (concat of <=4 row segments)
// =====================================================================
__global__ void conv_a_kernel(const float* __restrict__ A0, const float* __restrict__ A1,
                              const float* __restrict__ A2, const float* __restrict__ A3,
                              int r1, int r2, int r3, int nrows, int dst_row0)
{
    int i = blockIdx.x * 256 + threadIdx.x;
    if (i >= nrows * 128) return;
    int row = i >> 7, c4 = (i & 127) * 4;
    const float* src; int lr;
    if (row < r1)      { src = A0; lr = row; }
    else if (row < r2) { src = A1; lr = row - r1; }
    else if (row < r3) { src = A2; lr = row - r2; }
    else               { src = A3; lr = row - r3; }
    float4 v = *(const float4*)(src + (size_t)lr * 512 + c4);
    uint32_t h0, l0, h1, l1;
    pack_hl(v.x, v.y, h0, l0);
    pack_hl(v.z, v.w, h1, l1);
    size_t o = (size_t)(dst_row0 + row) * 512 + c4;
    *(uint2*)&g_ahi[o] = make_uint2(h0, h1);
    *(uint2*)&g_alo[o] = make_uint2(l0, l1);
}

// =====================================================================
// pos split: g_pos (192x512 fp32; row 191 zero) -> g_poshi/g_poslo
// =====================================================================
__global__ void conv_pos_kernel()
{
    int i = blockIdx.x * 256 + threadIdx.x;   // 192*256 threads, 2 floats each
    if (i >= 192 * 256) return;
    int row = i >> 8, c2 = (i & 255) * 2;
    float2 v = *(const float2*)(g_pos + (size_t)row * 512 + c2);
    uint32_t hi, lo;
    pack_hl(v.x, v.y, hi, lo);
    *(uint32_t*)&g_poshi[(size_t)row * 512 + c2] = hi;
    *(uint32_t*)&g_poslo[(size_t)row * 512 + c2] = lo;
}

// =====================================================================
// GEMM mainloop: 128x128 tile, cp.async 3-stage, 24 chunks
// =====================================================================
#define GSM_TOTAL 98304

#define GEMM_MAINLOOP(AHI, ALO, WHI, WLO, MRTOT)                                    \
    float acc[2][8][4] = {};                                                        \
    {                                                                               \
        auto issue = [&](int cc) {                                                  \
            const int seg = cc >> 3;                                                \
            const int k0 = (cc & 7) * 64;                                           \
            const __nv_bfloat16* asrc = (seg == 1) ? (ALO) : (AHI);                 \
            const __nv_bfloat16* wsrc = (seg == 2) ? (WLO) : (WHI);                 \
            char* abuf = gsm + (cc % 3) * 16384;                                    \
            char* bbuf = gsm + 49152 + (cc % 3) * 16384;                            \
            _Pragma("unroll")                                                       \
            for (int t = 0; t < 4; t++) {                                           \
                int ar = car + t * 32;                                              \
                int gr = row0 + ar; if (gr >= (MRTOT)) gr = (MRTOT) - 1;            \
                cpa16(smem_u32(abuf) + SWZ128((uint32_t)(ar * 128 + cg8 * 16)),     \
                      asrc + (size_t)gr * 512 + k0 + cg8 * 8);                      \
            }                                                                       \
            _Pragma("unroll")                                                       \
            for (int t = 0; t < 4; t++) {                                           \
                int br = car + t * 32;                                              \
                cpa16(smem_u32(bbuf) + SWZ128((uint32_t)(br * 128 + cg8 * 16)),     \
                      wsrc + (size_t)(col0 + br) * 512 + k0 + cg8 * 8);             \
            }                                                                       \
            CPA_COMMIT();                                                           \
        };                                                                          \
        issue(0);                                                                   \
        issue(1);                                                                   \
        const int l15 = lane & 15, lh = lane >> 4;                                  \
        const int l8 = lane & 7, lg = lane >> 3;                                    \
        for (int cc = 0; cc < 24; cc++) {                                           \
            if (cc < 23) CPA_WAIT1(); else CPA_WAIT0();                             \
            __syncthreads();                                                        \
            const uint32_t Ab = sb + (cc % 3) * 16384;                              \
            const uint32_t Bb = sb + 49152 + (cc % 3) * 16384;                      \
            _Pragma("unroll")                                                       \
            for (int s = 0; s < 4; s++) {                                           \
                uint32_t afr[2][4];                                                 \
                _Pragma("unroll")                                                   \
                for (int mt = 0; mt < 2; mt++) {                                    \
                    int r = wm * 32 + mt * 16 + l15;                                \
                    ldmx4(afr[mt], Ab + SWZ128((uint32_t)(r * 128 + s * 32 + lh * 16))); \
                }                                                                   \
                uint32_t bfr[4][4];                                                 \
                _Pragma("unroll")                                                   \
                for (int bt = 0; bt < 4; bt++) {                                    \
                    int n = wn * 64 + bt * 16 + ((lg >> 1) ? 8 : 0) + l8;           \
                    ldmx4(bfr[bt], Bb + SWZ128((uint32_t)(n * 128 + s * 32 + (lg & 1) * 16))); \
                }                                                                   \
                _Pragma("unroll")                                                   \
                for (int mt = 0; mt < 2; mt++)                                      \
                    _Pragma("unroll")                                               \
                    for (int nt = 0; nt < 8; nt++) {                                \
                        int bt = nt >> 1, sub = nt & 1;                             \
                        mma16816(acc[mt][nt], afr[mt], bfr[bt][2*sub], bfr[bt][2*sub+1]); \
                    }                                                               \
            }                                                                       \
            if (cc + 2 < 24) issue(cc + 2);                                         \
        }                                                                           \
    }

// ---- generic GEMM (pos / out projections) ----
__global__ __launch_bounds__(256, 2) void gemm_tc_kernel(
    const __nv_bfloat16* __restrict__ Ahi, const __nv_bfloat16* __restrict__ Alo,
    const __nv_bfloat16* __restrict__ Whib, const __nv_bfloat16* __restrict__ Wlob,
    float* __restrict__ Cm, int Mr, int ldc, const float* __restrict__ bias)
{
    extern __shared__ char gsm[];
    const uint32_t sb = smem_u32(gsm);
    const int tid = threadIdx.x;
    const int wid = tid >> 5, lane = tid & 31;
    const int wm = wid & 3, wn = wid >> 2;
    const int row0 = blockIdx.y * 128, col0 = blockIdx.x * 128;
    const int car = tid >> 3, cg8 = tid & 7;

    GEMM_MAINLOOP(Ahi, Alo, Whib, Wlob, Mr)

    const int quad = lane >> 2, tq = lane & 3;
    #pragma unroll
    for (int mt = 0; mt < 2; mt++) {
        #pragma unroll
        for (int nt = 0; nt < 8; nt++) {
            int gr0 = row0 + wm * 32 + mt * 16 + quad;
            int gc  = col0 + wn * 64 + nt * 8 + tq * 2;
            float b0 = bias ? bias[gc]     : 0.f;
            float b1 = bias ? bias[gc + 1] : 0.f;
            #pragma unroll
            for (int half = 0; half < 2; half++) {
                int gr = gr0 + half * 8;
                if (gr < Mr) {
                    float2 v = {acc[mt][nt][half*2+0] + b0, acc[mt][nt][half*2+1] + b1};
                    *(float2*)&Cm[(size_t)gr * ldc + gc] = v;
                }
            }
        }
    }
}

// ---- fused Q+KV GEMM ----
__global__ __launch_bounds__(256, 2) void gemm_qkv_kernel(
    const float* __restrict__ b_q, const float* __restrict__ b_kv)
{
    extern __shared__ char gsm[];
    const uint32_t sb = smem_u32(gsm);
    const int tid = threadIdx.x;
    const int wid = tid >> 5, lane = tid & 31;
    const int wm = wid & 3, wn = wid >> 2;
    const int row0 = blockIdx.y * 128, col0 = blockIdx.x * 128;
    const int car = tid >> 3, cg8 = tid & 7;

    GEMM_MAINLOOP(g_ahi, g_alo, g_whi, g_wlo, 8952)

    const int quad = lane >> 2, tq = lane & 3;
    const bool is_q = (col0 < 512);
    #pragma unroll
    for (int mt = 0; mt < 2; mt++) {
        #pragma unroll
        for (int nt = 0; nt < 8; nt++) {
            int gr0 = row0 + wm * 32 + mt * 16 + quad;
            int gc  = col0 + wn * 64 + nt * 8 + tq * 2;
            #pragma unroll
            for (int half = 0; half < 2; half++) {
                int gr = gr0 + half * 8;
                if (gr >= 8952) continue;
                float2 v = {acc[mt][nt][half*2+0], acc[mt][nt][half*2+1]};
                if (is_q) {
                    int qr = gr - 120;
                    if (qr >= 0) {
                        v.x += b_q[gc]; v.y += b_q[gc + 1];
                        *(float2*)&g_q[(size_t)qr * 512 + gc] = v;
                    }
                } else {
                    int kc = gc - 512;
                    if (gr < 8824) {
                        v.x += b_kv[kc]; v.y += b_kv[kc + 1];
                        *(float2*)&g_kv[(size_t)gr * 1024 + kc] = v;
                    }
                }
            }
        }
    }
}

// =====================================================================
// bu kernel: g_bu[bh][i] = pbu[h] . key[i]
// =====================================================================
__global__ void bu_kernel(const float* __restrict__ pbu)
{
    const int bh = blockIdx.y;
    const int b = bh >> 3, h = bh & 7;
    int i = blockIdx.x * 256 + threadIdx.x;
    if (i >= KV_) return;
    const float4* kp = (const float4*)(g_kv + ((size_t)i * B_ + b) * 1024 + h * 64);
    const float4* pp = (const float4*)(pbu + h * 64);
    float s = 0.f;
    #pragma unroll 4
    for (int k4 = 0; k4 < 16; k4++) {
        float4 kvv = kp[k4];
        float4 pv = pp[k4];
        s += pv.x * kvv.x + pv.y * kvv.y + pv.z * kvv.z + pv.w * kvv.w;
    }
    g_bu[(size_t)bh * 1104 + i] = s;
}

// =====================================================================
// bvp kernel: g_bvp[h][pl] = pbv[h] . pos[pl]
// =====================================================================
__global__ void bvp_kernel(const float* __restrict__ pbv)
{
    const int h = blockIdx.x;
    int pl = threadIdx.x;
    if (pl >= 192) return;
    float s = 0.f;
    if (pl < 191) {
        const float4* pp = (const float4*)(g_pos + (size_t)pl * 512 + h * 64);
        const float4* vp = (const float4*)(pbv + h * 64);
        #pragma unroll 4
        for (int k4 = 0; k4 < 16; k4++) {
            float4 a = pp[k4], bb = vp[k4];
            s += a.x * bb.x + a.y * bb.y + a.z * bb.z + a.w * bb.w;
        }
    }
    g_bvp[h * 192 + pl] = s;
}

// =====================================================================
// Fused attention v5: HMMA C1 + HMMA posS (BD band in-kernel) + softmax + HMMA PV
// 512 threads, ~221KB smem, 1 CTA/SM.
// =====================================================================
#define FZ_QHI 0
#define FZ_QLO 10240
#define FZ_KHI 20480
#define FZ_KLO 40960
#define FZ_POSHI 61440
#define FZ_POSLO 86016
#define FZ_SS   110592                 // scores fp32 stride 648B; P overlays (stride 336B)
#define FZ_PLO2 (FZ_SS + 26880)
#define FZ_PS   162432                 // posS fp32 80 x stride 776B
#define FZ_BU   224512                 // 160 f
#define FZ_BVP  225152                 // 192 f
#define FZ_TOTAL 225920

__global__ __launch_bounds__(512) void fused_attn_kernel(
    const int* __restrict__ lengths)
{
    extern __shared__ char fsm[];
    const uint32_t sb = smem_u32(fsm);
    float* bias_u  = (float*)(fsm + FZ_BU);
    float* bias_vp = (float*)(fsm + FZ_BVP);

    const int c = blockIdx.x, bh = blockIdx.y;
    const int b = bh >> 3, h = bh & 7;
    const int tid = threadIdx.x;
    const int wid = tid >> 5, lane = tid & 31;
    const int ustart = (c == 0) ? 0 : (c - 1) * CL_;
    const int ncols = c + 4 + ((c == 0) ? 64 : 128);
    const int len_b = lengths[b];
    const int pbase = (c == 0) ? 127 : 63;

    // ---- cp.async pos operand (bf16 hi/lo, 192 rows) ----
    for (int idx = tid; idx < 192 * 8; idx += 512) {
        int r = idx >> 3, ch = idx & 7;
        size_t go = (size_t)r * 512 + h * 64 + ch * 8;
        uint32_t so = SWZ128((uint32_t)(r * 128 + ch * 16));
        cpa16(sb + FZ_POSHI + so, g_poshi + go);
        cpa16(sb + FZ_POSLO + so, g_poslo + go);
    }
    CPA_COMMIT();

    // ---- convert Q (80 rows) fp32 -> bf16 hi/lo SW128 smem ----
    for (int idx = tid; idx < 80 * 32; idx += 512) {
        int r = idx >> 5, pr = idx & 31;
        uint32_t vhi = 0, vlo = 0;
        if (r < 69) {
            int qrow = (r < 4) ? c * 4 + r
                     : (r < 68 ? R_ + c * 64 + (r - 4) : R_ + U_ + c);
            float2 v = *(const float2*)(g_q + ((size_t)qrow * B_ + b) * 512 + h * 64 + pr * 2);
            pack_hl(v.x, v.y, vhi, vlo);
        }
        uint32_t off = SWZ128((uint32_t)(r * 128 + pr * 4));
        *(uint32_t*)(fsm + FZ_QHI + off) = vhi;
        *(uint32_t*)(fsm + FZ_QLO + off) = vlo;
    }
    // ---- convert K (160 rows) ----
    for (int idx = tid; idx < 160 * 32; idx += 512) {
        int r = idx >> 5, pr = idx & 31;
        uint32_t vhi = 0, vlo = 0;
        if (r < ncols) {
            int kvrow = kv_row_of(r, c, ustart);
            float2 v = *(const float2*)(g_kv + ((size_t)kvrow * B_ + b) * 1024 + h * 64 + pr * 2);
            pack_hl(v.x, v.y, vhi, vlo);
        }
        uint32_t off = SWZ128((uint32_t)(r * 128 + pr * 4));
        *(uint32_t*)(fsm + FZ_KHI + off) = vhi;
        *(uint32_t*)(fsm + FZ_KLO + off) = vlo;
    }
    if (tid < 160)
        bias_u[tid] = (tid < ncols) ? g_bu[(size_t)bh * 1104 + kv_row_of(tid, c, ustart)] : 0.f;
    else if (tid < 352)
        bias_vp[tid - 160] = g_bvp[h * 192 + (tid - 160)];
    CPA_WAIT0();
    __syncthreads();

    const int l15 = lane & 15, lh = lane >> 4;
    const int l8 = lane & 7, lg = lane >> 3;
    const int quad = lane >> 2, tq = lane & 3;
    const int wmc = wid / 3, wnc = wid % 3;   // wid 15 -> wmc 5 inactive

    // ---- C1: scores = Q.K^T (HMMA, 3 passes) ----
    if (wmc < 5) {
        float acc[4][2][4] = {};
        #pragma unroll
        for (int pass = 0; pass < 3; pass++) {
            const uint32_t Ab = sb + ((pass == 1) ? FZ_QLO : FZ_QHI);
            const uint32_t Bb = sb + ((pass == 2) ? FZ_KLO : FZ_KHI);
            #pragma unroll
            for (int s = 0; s < 4; s++) {
                uint32_t afr[4];
                ldmx4(afr, Ab + SWZ128((uint32_t)((wmc * 16 + l15) * 128 + s * 32 + lh * 16)));
                #pragma unroll
                for (int nj = 0; nj < 4; nj++) {
                    int nt = wnc + 3 * nj;
                    if (nt < 10) {
                        uint32_t bfr[4];
                        int n = nt * 16 + ((lg >> 1) ? 8 : 0) + l8;
                        ldmx4(bfr, Bb + SWZ128((uint32_t)(n * 128 + s * 32 + (lg & 1) * 16)));
                        mma16816(acc[nj][0], afr, bfr[0], bfr[1]);
                        mma16816(acc[nj][1], afr, bfr[2], bfr[3]);
                    }
                }
            }
        }
        #pragma unroll
        for (int nj = 0; nj < 4; nj++) {
            int nt = wnc + 3 * nj;
            if (nt < 10) {
                int r0 = wmc * 16 + quad;
                #pragma unroll
                for (int hf = 0; hf < 2; hf++) {
                    int col = nt * 16 + hf * 8 + tq * 2;
                    *(float2*)(fsm + FZ_SS + (size_t)r0 * 648 + col * 4) =
                        make_float2(acc[nj][hf][0], acc[nj][hf][1]);
                    *(float2*)(fsm + FZ_SS + (size_t)(r0 + 8) * 648 + col * 4) =
                        make_float2(acc[nj][hf][2], acc[nj][hf][3]);
                }
            }
        }
    }

    // ---- posS = Q.pos^T (HMMA, 3 passes, 12 n-tiles) ----
    if (wmc < 5) {
        float acc[4][2][4] = {};
        #pragma unroll
        for (int pass = 0; pass < 3; pass++) {
            const uint32_t Ab = sb + ((pass == 1) ? FZ_QLO : FZ_QHI);
            const uint32_t Bb = sb + ((pass == 2) ? FZ_POSLO : FZ_POSHI);
            #pragma unroll
            for (int s = 0; s < 4; s++) {
                uint32_t afr[4];
                ldmx4(afr, Ab + SWZ128((uint32_t)((wmc * 16 + l15) * 128 + s * 32 + lh * 16)));
                #pragma unroll
                for (int nj = 0; nj < 4; nj++) {
                    int nt = wnc + 3 * nj;   // 0..11
                    uint32_t bfr[4];
                    int n = nt * 16 + ((lg >> 1) ? 8 : 0) + l8;
                    ldmx4(bfr, Bb + SWZ128((uint32_t)(n * 128 + s * 32 + (lg & 1) * 16)));
                    mma16816(acc[nj][0], afr, bfr[0], bfr[1]);
                    mma16816(acc[nj][1], afr, bfr[2], bfr[3]);
                }
            }
        }
        #pragma unroll
        for (int nj = 0; nj < 4; nj++) {
            int nt = wnc + 3 * nj;
            int r0 = wmc * 16 + quad;
            #pragma unroll
            for (int hf = 0; hf < 2; hf++) {
                int col = nt * 16 + hf * 8 + tq * 2;
                *(float2*)(fsm + FZ_PS + (size_t)r0 * 776 + col * 4) =
                    make_float2(acc[nj][hf][0], acc[nj][hf][1]);
                *(float2*)(fsm + FZ_PS + (size_t)(r0 + 8) * 776 + col * 4) =
                    make_float2(acc[nj][hf][2], acc[nj][hf][3]);
            }
        }
    }
    __syncthreads();

    // ---- V conversion (overwrites K region) + softmax phase A ----
    float pvals[5][5];
    {
        for (int idx = tid; idx < 160 * 32; idx += 512) {
            int r = idx >> 5, pr = idx & 31;
            uint32_t vhi = 0, vlo = 0;
            if (r < ncols) {
                int kvrow = kv_row_of(r, c, ustart);
                float2 v = *(const float2*)(g_kv + ((size_t)kvrow * B_ + b) * 1024 + 512 + h * 64 + pr * 2);
                pack_hl(v.x, v.y, vhi, vlo);
            }
            uint32_t off = SWZ128((uint32_t)(r * 128 + pr * 4));
            *(uint32_t*)(fsm + FZ_KHI + off) = vhi;
            *(uint32_t*)(fsm + FZ_KLO + off) = vlo;
        }
        const int limit_j = len_b - ustart;
        const int uc0 = c + 4;
        int slot = 0;
        for (int r = wid; r < 69; r += 16, slot++) {
            const bool is_utt = (r >= 4) && (r < 68);
            const int plb = pbase - (r - 4) - uc0;   // pl = plb + i
            const char* psrow = fsm + FZ_PS + (size_t)r * 776;
            float vals[5];
            float mx = -3.4e38f;
            #pragma unroll
            for (int g = 0; g < 5; g++) {
                int i = lane + 32 * g;
                float v = -3.4e38f;
                if (i < ncols) {
                    float s = *(const float*)(fsm + FZ_SS + (size_t)r * 648 + i * 4) + bias_u[i];
                    if (i >= uc0) {
                        int j = i - uc0;
                        if (is_utt) {
                            int pl = plb + i;
                            s += *(const float*)(psrow + pl * 4) + bias_vp[pl];
                        }
                        v = (j >= limit_j) ? NEG_INF_ : s * SCALING_;
                    } else {
                        v = s * SCALING_;
                    }
                }
                vals[g] = v;
                mx = fmaxf(mx, v);
            }
            #pragma unroll
            for (int o = 16; o > 0; o >>= 1) mx = fmaxf(mx, __shfl_xor_sync(~0u, mx, o));
            float sum = 0.f;
            #pragma unroll
            for (int g = 0; g < 5; g++) {
                float e = __expf(vals[g] - mx);
                vals[g] = e;
                sum += e;
            }
            #pragma unroll
            for (int o = 16; o > 0; o >>= 1) sum += __shfl_xor_sync(~0u, sum, o);
            float inv = 1.f / sum;
            #pragma unroll
            for (int g = 0; g < 5; g++) pvals[slot][g] = vals[g] * inv;
        }
    }
    __syncthreads();

    // ---- phase B: write P bf16 hi/lo over score region + zero pads ----
    {
        int slot = 0;
        for (int r = wid; r < 69; r += 16, slot++) {
            #pragma unroll
            for (int g = 0; g < 5; g++) {
                int i = lane + 32 * g;
                float p = pvals[slot][g];
                __nv_bfloat16 hp = __float2bfloat16(p);
                __nv_bfloat16 lp = __float2bfloat16(p - __bfloat162float(hp));
                *(ushort*)(fsm + FZ_SS + r * 336 + i * 2) = __bfloat16_as_ushort(hp);
                *(ushort*)(fsm + FZ_PLO2 + r * 336 + i * 2) = __bfloat16_as_ushort(lp);
            }
        }
        for (int idx = tid; idx < 462; idx += 512) {
            *(u64t*)(fsm + FZ_SS + 23184 + idx * 8) = 0ull;
            *(u64t*)(fsm + FZ_PLO2 + 23184 + idx * 8) = 0ull;
        }
    }
    __syncthreads();

    // ---- PV: out = P.V (HMMA, 3 passes) ----
    {
        const int wmp = wid >> 2, wnp = wid & 3;
        float accp[2][2][4] = {};
        #pragma unroll
        for (int pass = 0; pass < 3; pass++) {
            const uint32_t Ab = sb + ((pass == 1) ? FZ_PLO2 : FZ_SS);
            const uint32_t Bb = sb + ((pass == 2) ? FZ_KLO : FZ_KHI);
            #pragma unroll
            for (int kk = 0; kk < 10; kk++) {
                uint32_t bfr[4];
                ldmx4t(bfr, Bb + SWZ128((uint32_t)((kk * 16 + l15) * 128 + wnp * 32 + lh * 16)));
                #pragma unroll
                for (int mi = 0; mi < 2; mi++) {
                    int m = wmp + 4 * mi;
                    if (m < 5) {
                        uint32_t afr[4];
                        ldmx4(afr, Ab + (uint32_t)((m * 16 + l15) * 336 + kk * 32 + lh * 16));
                        mma16816(accp[mi][0], afr, bfr[0], bfr[1]);
                        mma16816(accp[mi][1], afr, bfr[2], bfr[3]);
                    }
                }
            }
        }
        #pragma unroll
        for (int mi = 0; mi < 2; mi++) {
            int m = wmp + 4 * mi;
            if (m >= 5) continue;
            int r0 = m * 16 + quad;
            #pragma unroll
            for (int hf = 0; hf < 2; hf++) {
                int r = r0 + hf * 8;
                if (r < 68) {
                    int qrow = (r < 4) ? c * 4 + r : R_ + c * 64 + (r - 4);
                    size_t base = ((size_t)qrow * B_ + b) * 512 + h * 64;
                    #pragma unroll
                    for (int n = 0; n < 2; n++) {
                        int d = wnp * 16 + n * 8 + tq * 2;
                        uint32_t vhi, vlo;
                        pack_hl(accp[mi][n][hf*2+0], accp[mi][n][hf*2+1], vhi, vlo);
                        *(uint32_t*)&g_ahi[base + d] = vhi;
                        *(uint32_t*)&g_alo[base + d] = vlo;
                    }
                } else if (r == 68) {
                    int qrow = R_ + U_ + c;
                    float* dst = g_attn + ((size_t)qrow * B_ + b) * 512 + h * 64;
                    #pragma unroll
                    for (int n = 0; n < 2; n++) {
                        int d = wnp * 16 + n * 8 + tq * 2;
                        *(float2*)(dst + d) =
                            make_float2(accp[mi][n][hf*2+0], accp[mi][n][hf*2+1]);
                    }
                }
            }
        }
    }
}

// ---------------- out_mem = clip(attn[R+U:], -10, 10) ----------------
__global__ void clip_kernel(float* __restrict__ out)
{
    const size_t off = (size_t)(R_ + U_) * B_ * D_;
    int i = blockIdx.x * 256 + threadIdx.x;
    float v = g_attn[off + i];
    out[off + i] = fminf(10.f, fmaxf(-10.f, v));
}

// ---------------- launch ----------------
extern "C" void kernel_launch(void* const* d_in, const int* in_sizes, int n_in,
                              void* d_out, int out_size)
{
    const float* utt    = (const float*)d_in[0];
    const int*   lens   = (const int*)  d_in[1];
    const float* rc     = (const float*)d_in[2];
    const float* summ   = (const float*)d_in[3];
    const float* mem    = (const float*)d_in[4];
    const float* pos_e  = (const float*)d_in[6];
    const float* W_kv   = (const float*)d_in[7];
    const float* b_kv   = (const float*)d_in[8];
    const float* W_q    = (const float*)d_in[9];
    const float* b_q    = (const float*)d_in[10];
    const float* W_out  = (const float*)d_in[11];
    const float* b_out  = (const float*)d_in[12];
    const float* W_pos  = (const float*)d_in[13];
    const float* pbu    = (const float*)d_in[14];
    const float* pbv    = (const float*)d_in[15];
    float* out = (float*)d_out;

    float *pos_buf;
    __nv_bfloat16 *ahi, *alo, *whi, *wlo;
    cudaGetSymbolAddress((void**)&pos_buf, g_pos);
    cudaGetSymbolAddress((void**)&ahi,     g_ahi);
    cudaGetSymbolAddress((void**)&alo,     g_alo);
    cudaGetSymbolAddress((void**)&whi,     g_whi);
    cudaGetSymbolAddress((void**)&wlo,     g_wlo);

    cudaFuncSetAttribute(fused_attn_kernel,
                         cudaFuncAttributeMaxDynamicSharedMemorySize, FZ_TOTAL);
    cudaFuncSetAttribute(gemm_tc_kernel,
                         cudaFuncAttributeMaxDynamicSharedMemorySize, GSM_TOTAL);
    cudaFuncSetAttribute(gemm_qkv_kernel,
                         cudaFuncAttributeMaxDynamicSharedMemorySize, GSM_TOTAL);

    const dim3 blk(256);
    const float* pos_src = pos_e + (size_t)(U_ - 128) * D_;

    // ---- conversions ----
    conv_a_kernel<<<dim3((8952 * 128 + 255) / 256), blk>>>(
        mem, rc, utt, summ, 120, 632, 8824, 8952, 0);
    conv_a_kernel<<<dim3((191 * 128 + 255) / 256), blk>>>(
        pos_src, pos_src, pos_src, pos_src, 191, 191, 191, 191, 8952);
    conv_w_all<<<dim3(2560 * 512 / 256), blk>>>(W_q, W_kv, W_out, W_pos);

    // ---- fused Q+KV projection ----
    gemm_qkv_kernel<<<dim3(12, 70), blk, GSM_TOTAL>>>(b_q, b_kv);

    // ---- pos projection (fp32 out) then bf16 split ----
    gemm_tc_kernel<<<dim3(4, 2), blk, GSM_TOTAL>>>(
        ahi + (size_t)8952 * 512, alo + (size_t)8952 * 512,
        whi + (size_t)2048 * 512, wlo + (size_t)2048 * 512,
        pos_buf, 191, D_, nullptr);
    conv_pos_kernel<<<dim3(192), blk>>>();

    // ---- attention ----
    bu_kernel<<<dim3(5, 64), blk>>>(pbu);
    bvp_kernel<<<dim3(8), blk>>>(pbv);
    fused_attn_kernel<<<dim3(C_, 64), dim3(512), FZ_TOTAL>>>(lens);

    // ---- output projection ----
    gemm_tc_kernel<<<dim3(4, 68), blk, GSM_TOTAL>>>(
        ahi, alo, whi + (size_t)1536 * 512, wlo + (size_t)1536 * 512,
        out, (R_ + U_) * B_, D_, b_out);
    clip_kernel<<<dim3(256), blk>>>(out);
}